// round 3
// baseline (speedup 1.0000x reference)
#include <cuda_runtime.h>
#include <math.h>

// ---------------- problem constants ----------------
#define BB 64
#define TT 256
#define LL 16
#define VC 100
#define DC 50
#define CHN 100
#define DW 300
#define DF 20
#define HH 256
#define IND 420          // DW + CHN + DF
#define NT 52            // LAB + 2
#define TSTART 50
#define TSTOP 51
#define NBLK_LSTM 128

// ---------------- scratch (device globals; no allocations) ----------------
__device__ float d_tbl[3][VC][CHN];                 // conv lookup table
__device__ float d_x[(size_t)TT * BB * IND];        // x, row = t*BB + b
__device__ float d_xs[2][TT][4 * HH][BB];           // input proj, transposed [t][n][b]
__device__ float d_hseq[2][TT][HH][BB];             // per-step hidden states
__device__ float d_feats[(size_t)TT * BB * NT];     // emissions [t][b][n]
__device__ unsigned char d_bp[(size_t)TT * BB * NT];// viterbi backpointers
__device__ float d_lossp[BB];
__device__ unsigned d_bar_cnt = 0;
__device__ unsigned d_bar_gen = 0;

// ---------------- 1. conv -> lookup table ----------------
__global__ void k_table(const float* __restrict__ conv_w,
                        const float* __restrict__ char_emb) {
    int idx = blockIdx.x * blockDim.x + threadIdx.x;
    if (idx >= 3 * VC * CHN) return;
    int ch = idx % CHN;
    int c  = (idx / CHN) % VC;
    int kk = idx / (CHN * VC);
    float s = 0.f;
    #pragma unroll 10
    for (int dc = 0; dc < DC; dc++)
        s += conv_w[(ch * DC + dc) * 3 + kk] * char_emb[c * DC + dc];
    d_tbl[kk][c][ch] = s;
}

// ---------------- 2. build x = [word_emb | char_cnn | feat_emb] ----------------
__global__ void k_build_x(const int* __restrict__ word,
                          const int* __restrict__ featidx,
                          const int* __restrict__ chars,
                          const int* __restrict__ recover,
                          const float* __restrict__ word_emb,
                          const float* __restrict__ feat_emb,
                          const float* __restrict__ conv_b) {
    int m = blockIdx.x;           // row = t*BB + b
    int t = m / BB, b = m % BB;
    int tid = threadIdx.x;
    __shared__ int cs[LL];
    float* xr = &d_x[(size_t)m * IND];
    int w = word[b * TT + t];
    for (int i = tid; i < DW; i += blockDim.x) xr[i] = word_emb[w * DW + i];
    if (tid < DF) {
        int fv = featidx[b];
        xr[DW + CHN + tid] = feat_emb[fv * DF + tid];
    }
    if (tid < LL) {
        int j = recover[b * TT + t];
        cs[tid] = chars[j * LL + tid];
    }
    __syncthreads();
    if (tid < CHN) {
        float bias = conv_b[tid];
        float mx = -3.4e38f;
        #pragma unroll
        for (int l = 0; l < LL; l++) {
            float v = bias + d_tbl[1][cs[l]][tid];
            if (l > 0)       v += d_tbl[0][cs[l - 1]][tid];
            if (l < LL - 1)  v += d_tbl[2][cs[l + 1]][tid];
            mx = fmaxf(mx, v);
        }
        xr[DW + tid] = mx;
    }
}

// ---------------- 3. input projection GEMM: out[t][n][b] = x[t*64+b,:] . W[n,:] + bias[n] ----------------
__global__ void __launch_bounds__(256) k_gemm(int dir,
                                              const float* __restrict__ W,
                                              const float* __restrict__ bias) {
    __shared__ float As[16][64];
    __shared__ float Bs[16][64];
    int t  = blockIdx.x;
    int n0 = blockIdx.y * 64;
    int tid = threadIdx.x;
    int bq = tid & 15;        // covers b = bq*4 + i
    int nq = tid >> 4;        // covers n = n0 + nq*4 + j
    int lr = tid >> 2;        // tile row for loads (0..63)
    int lk = (tid & 3) * 4;   // k offset for float4 load

    float acc[4][4];
    #pragma unroll
    for (int i = 0; i < 4; i++)
        #pragma unroll
        for (int j = 0; j < 4; j++) acc[i][j] = 0.f;

    const float* Arow = &d_x[(size_t)(t * 64 + lr) * IND];
    const float* Brow = &W[(size_t)(n0 + lr) * IND];
    float* out = &d_xs[dir][0][0][0];

    for (int k0 = 0; k0 < IND; k0 += 16) {
        float4 av = make_float4(0.f, 0.f, 0.f, 0.f);
        float4 bv = make_float4(0.f, 0.f, 0.f, 0.f);
        if (k0 + lk < IND) {                       // IND % 4 == 0 -> all-or-nothing
            av = *(const float4*)(Arow + k0 + lk);
            bv = *(const float4*)(Brow + k0 + lk);
        }
        As[lk + 0][lr] = av.x; As[lk + 1][lr] = av.y;
        As[lk + 2][lr] = av.z; As[lk + 3][lr] = av.w;
        Bs[lk + 0][lr] = bv.x; Bs[lk + 1][lr] = bv.y;
        Bs[lk + 2][lr] = bv.z; Bs[lk + 3][lr] = bv.w;
        __syncthreads();
        #pragma unroll
        for (int k = 0; k < 16; k++) {
            float4 a = *(const float4*)&As[k][bq * 4];
            float4 bvv = *(const float4*)&Bs[k][nq * 4];
            acc[0][0] += a.x * bvv.x; acc[0][1] += a.x * bvv.y;
            acc[0][2] += a.x * bvv.z; acc[0][3] += a.x * bvv.w;
            acc[1][0] += a.y * bvv.x; acc[1][1] += a.y * bvv.y;
            acc[1][2] += a.y * bvv.z; acc[1][3] += a.y * bvv.w;
            acc[2][0] += a.z * bvv.x; acc[2][1] += a.z * bvv.y;
            acc[2][2] += a.z * bvv.z; acc[2][3] += a.z * bvv.w;
            acc[3][0] += a.w * bvv.x; acc[3][1] += a.w * bvv.y;
            acc[3][2] += a.w * bvv.z; acc[3][3] += a.w * bvv.w;
        }
        __syncthreads();
    }
    #pragma unroll
    for (int j = 0; j < 4; j++) {
        int n = n0 + nq * 4 + j;
        float bz = bias[n];
        float4 o;
        o.x = acc[0][j] + bz; o.y = acc[1][j] + bz;
        o.z = acc[2][j] + bz; o.w = acc[3][j] + bz;
        *(float4*)&out[((size_t)t * 1024 + n) * 64 + bq * 4] = o;
    }
}

// ---------------- 4. persistent bidirectional LSTM ----------------
__global__ void __launch_bounds__(256, 1) k_lstm(const float* __restrict__ whh_f,
                                                 const float* __restrict__ whh_b,
                                                 const int* __restrict__ lens) {
    __shared__ float Ws[4][4][HH];   // [gate][unit][k]  16 KB
    __shared__ float hs[64][64];     // h chunk          16 KB
    int blk = blockIdx.x;
    int dir = blk >> 6;
    int ub  = (blk & 63) * 4;
    int tid = threadIdx.x;
    int uj  = tid >> 6;              // unit within block 0..3
    int b   = tid & 63;              // batch lane
    const float* whh = dir ? whh_b : whh_f;

    for (int i = tid; i < 4 * 4 * HH; i += 256) {
        int k = i & (HH - 1);
        int j = (i >> 8) & 3;
        int g = i >> 10;
        Ws[g][j][k] = whh[(size_t)(g * HH + ub + j) * HH + k];
    }
    int len_b = lens[b];
    int u = ub + uj;
    float c = 0.f, h = 0.f;
    unsigned gen = atomicAdd(&d_bar_gen, 0u);     // stable: no bump until all arrive
    const float* xs_base = &d_xs[dir][0][0][0];
    float* hq_base = &d_hseq[dir][0][0][0];
    __syncthreads();

    for (int s = 0; s < TT; s++) {
        int t = dir ? (TT - 1 - s) : s;
        float a0 = 0.f, a1 = 0.f, a2 = 0.f, a3 = 0.f;
        if (s > 0) {
            int tp = dir ? (t + 1) : (t - 1);
            const float* hprev = hq_base + (size_t)tp * HH * BB;
            #pragma unroll
            for (int c4 = 0; c4 < 4; c4++) {
                #pragma unroll
                for (int i = 0; i < 16; i++) {
                    int idx = tid + i * 256;
                    hs[idx >> 6][idx & 63] = hprev[c4 * 64 * 64 + idx];
                }
                __syncthreads();
                const float* w0 = &Ws[0][uj][c4 * 64];
                const float* w1 = &Ws[1][uj][c4 * 64];
                const float* w2 = &Ws[2][uj][c4 * 64];
                const float* w3 = &Ws[3][uj][c4 * 64];
                #pragma unroll
                for (int k = 0; k < 64; k += 4) {
                    float4 v0 = *(const float4*)(w0 + k);
                    float4 v1 = *(const float4*)(w1 + k);
                    float4 v2 = *(const float4*)(w2 + k);
                    float4 v3 = *(const float4*)(w3 + k);
                    float h0 = hs[k][b], h1 = hs[k + 1][b];
                    float h2 = hs[k + 2][b], h3 = hs[k + 3][b];
                    a0 += h0 * v0.x + h1 * v0.y + h2 * v0.z + h3 * v0.w;
                    a1 += h0 * v1.x + h1 * v1.y + h2 * v1.z + h3 * v1.w;
                    a2 += h0 * v2.x + h1 * v2.y + h2 * v2.z + h3 * v2.w;
                    a3 += h0 * v3.x + h1 * v3.y + h2 * v3.z + h3 * v3.w;
                }
                __syncthreads();
            }
        }
        const float* xsp = xs_base + (size_t)t * 1024 * 64;
        float g0 = xsp[(0 * HH + u) * 64 + b] + a0;
        float g1 = xsp[(1 * HH + u) * 64 + b] + a1;
        float g2 = xsp[(2 * HH + u) * 64 + b] + a2;
        float g3 = xsp[(3 * HH + u) * 64 + b] + a3;
        float ig = 1.f / (1.f + expf(-g0));
        float fg = 1.f / (1.f + expf(-g1));
        float gg = tanhf(g2);
        float og = 1.f / (1.f + expf(-g3));
        float cn = fg * c + ig * gg;
        float hn = og * tanhf(cn);
        if (t < len_b) { c = cn; h = hn; }
        hq_base[((size_t)t * HH + u) * BB + b] = h;

        // grid barrier (generation based; survives graph replays)
        __syncthreads();
        if (tid == 0) {
            unsigned target = gen + 1;
            __threadfence();
            if (atomicAdd(&d_bar_cnt, 1u) == (unsigned)(NBLK_LSTM - 1)) {
                atomicExch(&d_bar_cnt, 0u);
                __threadfence();
                atomicExch(&d_bar_gen, target);
            } else {
                while (*(volatile unsigned*)&d_bar_gen != target) { }
                __threadfence();
            }
        }
        gen++;
        __syncthreads();
    }
}

// ---------------- 5. projection + mask -> feats[t][b][n] ----------------
__global__ void __launch_bounds__(256) k_proj(const float* __restrict__ proj_w,
                                              const float* __restrict__ proj_b,
                                              const int* __restrict__ lens) {
    __shared__ float hsm[64][64];
    __shared__ float pw[NT][64];
    int t = blockIdx.x;
    int tid = threadIdx.x;
    int b = tid & 63, grp = tid >> 6;      // 4 groups x 13 labels
    float acc[13];
    #pragma unroll
    for (int r = 0; r < 13; r++) acc[r] = 0.f;

    for (int kc = 0; kc < 8; kc++) {
        int u512 = kc * 64;
        int dir = u512 >> 8;
        int ubo = u512 & 255;
        const float* hp = &d_hseq[dir][t][ubo][0];
        #pragma unroll
        for (int i = 0; i < 16; i++) {
            int idx = tid + i * 256;
            hsm[idx >> 6][idx & 63] = hp[idx];
        }
        for (int i = tid; i < NT * 64; i += 256) {
            int n = i >> 6, k = i & 63;
            pw[n][k] = proj_w[(size_t)n * (2 * HH) + kc * 64 + k];
        }
        __syncthreads();
        for (int k = 0; k < 64; k++) {
            float hv = hsm[k][b];
            #pragma unroll
            for (int r = 0; r < 13; r++)
                acc[r] += hv * pw[grp * 13 + r][k];
        }
        __syncthreads();
    }
    int msk = (t < lens[b]) ? 1 : 0;
    #pragma unroll
    for (int r = 0; r < 13; r++) {
        int n = grp * 13 + r;
        d_feats[((size_t)t * 64 + b) * NT + n] = (msk ? acc[r] : 0.f) + proj_b[n];
    }
}

// ---------------- 6. CRF: forward Z + viterbi + gold + tags ----------------
__global__ void __launch_bounds__(64) k_crf(const float* __restrict__ transitions,
                                            const int* __restrict__ lens,
                                            const int* __restrict__ labels,
                                            float* __restrict__ out) {
    __shared__ float tr[NT * NT];
    __shared__ float E[NT * NT];
    __shared__ float alpha[64], vv[64], ea[64], red[64];
    int b = blockIdx.x;
    int j = threadIdx.x;

    for (int i = j; i < NT * NT; i += 64) {
        float x = transitions[i];
        tr[i] = x;
        E[i] = expf(x);                 // exp(-1e4) == 0 exactly
    }
    __syncthreads();
    int len = lens[b];

    float aj = -INFINITY;
    if (j < NT) aj = d_feats[(size_t)(0 * 64 + b) * NT + j] + tr[TSTART * NT + j];
    alpha[j] = aj;
    vv[j] = aj;
    __syncthreads();

    for (int t = 1; t < len; t++) {
        red[j] = (j < NT) ? alpha[j] : -INFINITY;
        __syncthreads();
        for (int off = 32; off >= 1; off >>= 1) {
            if (j < off) red[j] = fmaxf(red[j], red[j + off]);
            __syncthreads();
        }
        float m = red[0];
        ea[j] = (j < NT) ? expf(alpha[j] - m) : 0.f;
        __syncthreads();
        float s = 0.f, best = -INFINITY, f = 0.f;
        int bp = 0;
        if (j < NT) {
            f = d_feats[((size_t)t * 64 + b) * NT + j];
            #pragma unroll 4
            for (int i = 0; i < NT; i++) s += ea[i] * E[i * NT + j];
            // reference rounding order: cand = v[i] + (f[j] + T[i][j]); f INSIDE the max
            for (int i = 0; i < NT; i++) {
                float sij = f + tr[i * NT + j];
                float cnd = vv[i] + sij;
                if (cnd > best) { best = cnd; bp = i; }
            }
        }
        __syncthreads();
        if (j < NT) {
            alpha[j] = m + logf(s) + f;
            vv[j] = best;
            d_bp[((size_t)t * 64 + b) * NT + j] = (unsigned char)bp;
        }
        __syncthreads();
    }

    // ---- Z = logsumexp(alpha + tr[:,STOP]) ----
    float zx = (j < NT) ? alpha[j] + tr[j * NT + TSTOP] : -INFINITY;
    red[j] = zx;
    __syncthreads();
    for (int off = 32; off >= 1; off >>= 1) {
        if (j < off) red[j] = fmaxf(red[j], red[j + off]);
        __syncthreads();
    }
    float zm = red[0];
    __syncthreads();
    red[j] = (j < NT) ? expf(zx - zm) : 0.f;
    __syncthreads();
    for (int off = 32; off >= 1; off >>= 1) {
        if (j < off) red[j] += red[j + off];
        __syncthreads();
    }
    float Z = zm + logf(red[0]);
    __syncthreads();

    // ---- best last tag: exact first-index argmax (sequential, jnp.argmax semantics) ----
    red[j] = (j < NT) ? vv[j] + tr[j * NT + TSTOP] : -INFINITY;
    __syncthreads();
    __shared__ int s_best_last;
    if (j == 0) {
        float bv = -INFINITY; int bi = 0;
        for (int i = 0; i < NT; i++) {
            if (red[i] > bv) { bv = red[i]; bi = i; }
        }
        s_best_last = bi;
    }
    __syncthreads();
    int best_last = s_best_last;
    __syncthreads();

    // ---- gold score ----
    float gp = 0.f;
    for (int t = j; t < TT; t += 64) {
        if (t < len) {
            int lab = labels[b * TT + t];
            gp += d_feats[((size_t)t * 64 + b) * NT + lab];
            if (t >= 1) gp += tr[labels[b * TT + t - 1] * NT + lab];
        }
    }
    red[j] = gp;
    __syncthreads();
    for (int off = 32; off >= 1; off >>= 1) {
        if (j < off) red[j] += red[j + off];
        __syncthreads();
    }
    if (j == 0) {
        int l0 = labels[b * TT + 0];
        int ll = labels[b * TT + len - 1];
        float gold = red[0] + tr[TSTART * NT + l0] + tr[ll * NT + TSTOP];
        d_lossp[b] = Z - gold;
    }

    // ---- backtrack + write tags (identity bp beyond len) ----
    if (j == 0) {
        int cur = best_last;
        for (int t = TT - 1; t >= 0; --t) {
            out[1 + b * TT + t] = (t < len) ? (float)cur : 0.f;
            if (t > 0 && t < len) cur = (int)d_bp[((size_t)t * 64 + b) * NT + cur];
        }
    }
}

// ---------------- 7. loss reduction ----------------
__global__ void k_loss(float* __restrict__ out) {
    __shared__ float red[64];
    int j = threadIdx.x;
    red[j] = d_lossp[j];
    __syncthreads();
    for (int off = 32; off >= 1; off >>= 1) {
        if (j < off) red[j] += red[j + off];
        __syncthreads();
    }
    if (j == 0) out[0] = red[0];
}

// ---------------- launch ----------------
extern "C" void kernel_launch(void* const* d_in, const int* in_sizes, int n_in,
                              void* d_out, int out_size) {
    const int*   batch_word     = (const int*)  d_in[0];
    const int*   batch_features = (const int*)  d_in[1];
    const int*   batch_wordlen  = (const int*)  d_in[2];
    const int*   batch_char     = (const int*)  d_in[3];
    /* d_in[4] batch_charlen unused */
    const int*   charrecover    = (const int*)  d_in[5];
    /* d_in[6] mask unused (derived from lengths) */
    const int*   batch_label    = (const int*)  d_in[7];
    const float* char_emb       = (const float*)d_in[8];
    const float* conv_w         = (const float*)d_in[9];
    const float* conv_b         = (const float*)d_in[10];
    const float* word_emb       = (const float*)d_in[11];
    const float* feat_emb       = (const float*)d_in[12];
    const float* w_ih_f         = (const float*)d_in[13];
    const float* w_hh_f         = (const float*)d_in[14];
    const float* b_f            = (const float*)d_in[15];
    const float* w_ih_b         = (const float*)d_in[16];
    const float* w_hh_b         = (const float*)d_in[17];
    const float* b_b            = (const float*)d_in[18];
    const float* proj_w         = (const float*)d_in[19];
    const float* proj_b         = (const float*)d_in[20];
    const float* transitions    = (const float*)d_in[21];
    float* out = (float*)d_out;
    (void)in_sizes; (void)n_in; (void)out_size;

    k_table<<<(3 * VC * CHN + 255) / 256, 256>>>(conv_w, char_emb);
    k_build_x<<<TT * BB, 128>>>(batch_word, batch_features, batch_char,
                                charrecover, word_emb, feat_emb, conv_b);
    {
        dim3 g(TT, (4 * HH) / 64);
        k_gemm<<<g, 256>>>(0, w_ih_f, b_f);
        k_gemm<<<g, 256>>>(1, w_ih_b, b_b);
    }
    k_lstm<<<NBLK_LSTM, 256>>>(w_hh_f, w_hh_b, batch_wordlen);
    k_proj<<<TT, 256>>>(proj_w, proj_b, batch_wordlen);
    k_crf<<<BB, 64>>>(transitions, batch_wordlen, batch_label, out);
    k_loss<<<1, 64>>>(out);
}

// round 4
// speedup vs baseline: 1.2550x; 1.2550x over previous
#include <cuda_runtime.h>
#include <math.h>

// ---------------- problem constants ----------------
#define BB 64
#define TT 256
#define LL 16
#define VC 100
#define DC 50
#define CHN 100
#define DW 300
#define DF 20
#define HH 256
#define IND 420          // DW + CHN + DF
#define NT 52            // LAB + 2
#define TSTART 50
#define TSTOP 51
#define NBLK_DIR 64      // LSTM blocks per direction

// ---------------- scratch (device globals; no allocations) ----------------
__device__ float d_tbl[3][VC][CHN];                 // conv lookup table
__device__ float d_x[(size_t)TT * BB * IND];        // x, row = t*BB + b
__device__ float d_xs[2][TT][4 * HH][BB];           // input proj, transposed [t][n][b]
__device__ float d_hseq[2][TT][HH][BB];             // per-step hidden states
__device__ float d_feats[(size_t)TT * BB * NT];     // emissions [t][b][n]
__device__ float d_lossp[BB];
__device__ unsigned d_bc[2] = {0, 0};               // per-direction barrier count
__device__ unsigned d_bg[2] = {0, 0};               // per-direction barrier gen

// ---------------- 1. conv -> lookup table ----------------
__global__ void k_table(const float* __restrict__ conv_w,
                        const float* __restrict__ char_emb) {
    int idx = blockIdx.x * blockDim.x + threadIdx.x;
    if (idx >= 3 * VC * CHN) return;
    int ch = idx % CHN;
    int c  = (idx / CHN) % VC;
    int kk = idx / (CHN * VC);
    float s = 0.f;
    #pragma unroll 10
    for (int dc = 0; dc < DC; dc++)
        s += conv_w[(ch * DC + dc) * 3 + kk] * char_emb[c * DC + dc];
    d_tbl[kk][c][ch] = s;
}

// ---------------- 2. build x = [word_emb | char_cnn | feat_emb] ----------------
__global__ void k_build_x(const int* __restrict__ word,
                          const int* __restrict__ featidx,
                          const int* __restrict__ chars,
                          const int* __restrict__ recover,
                          const float* __restrict__ word_emb,
                          const float* __restrict__ feat_emb,
                          const float* __restrict__ conv_b) {
    int m = blockIdx.x;           // row = t*BB + b
    int t = m / BB, b = m % BB;
    int tid = threadIdx.x;
    __shared__ int cs[LL];
    float* xr = &d_x[(size_t)m * IND];
    int w = word[b * TT + t];
    // word emb: 300 floats = 75 float4 (both bases 16B aligned)
    const float4* we4 = (const float4*)(word_emb + (size_t)w * DW);
    float4* xr4 = (float4*)xr;
    for (int i = tid; i < DW / 4; i += blockDim.x) xr4[i] = we4[i];
    if (tid < DF) {
        int fv = featidx[b];
        xr[DW + CHN + tid] = feat_emb[fv * DF + tid];
    }
    if (tid < LL) {
        int j = recover[b * TT + t];
        cs[tid] = chars[j * LL + tid];
    }
    __syncthreads();
    if (tid < CHN) {
        float bias = conv_b[tid];
        float mx = -3.4e38f;
        #pragma unroll
        for (int l = 0; l < LL; l++) {
            float v = bias + d_tbl[1][cs[l]][tid];
            if (l > 0)       v += d_tbl[0][cs[l - 1]][tid];
            if (l < LL - 1)  v += d_tbl[2][cs[l + 1]][tid];
            mx = fmaxf(mx, v);
        }
        xr[DW + tid] = mx;
    }
}

// ---------------- 3. input projection GEMM (fused over t, both dirs) ----------------
// C[m][n] = x[m,:] . W[n,:] + bias[n], m = t*64+b (M=16384), N=1024, K=420
// stored as d_xs[dir][t][n][b]. 128x128x16 tiles, 8x8 microtile, double buffer.
__global__ void __launch_bounds__(256, 2) k_gemm2(const float* __restrict__ w_f,
                                                  const float* __restrict__ b_fp,
                                                  const float* __restrict__ w_b,
                                                  const float* __restrict__ b_bp) {
    __shared__ float As[2][16][128];
    __shared__ float Bs[2][16][128];
    int dir = blockIdx.z;
    const float* W    = dir ? w_b  : w_f;
    const float* bias = dir ? b_bp : b_fp;
    int m0 = blockIdx.x * 128;
    int n0 = blockIdx.y * 128;
    int tid = threadIdx.x;
    int bq = tid & 15;            // m micro-tile: rows bq*8 .. bq*8+7
    int nq = tid >> 4;            // n micro-tile: cols nq*8 .. nq*8+7

    // load ids: 512 float4 per tile per matrix; this thread handles tid, tid+256
    int r0 = tid >> 2,        kq0 = (tid & 3) << 2;
    int r1 = (tid + 256) >> 2, kq1 = ((tid + 256) & 3) << 2;

    const float* A0 = &d_x[(size_t)(m0 + r0) * IND];
    const float* A1 = &d_x[(size_t)(m0 + r1) * IND];
    const float* B0 = &W[(size_t)(n0 + r0) * IND];
    const float* B1 = &W[(size_t)(n0 + r1) * IND];

    float acc[8][8];
    #pragma unroll
    for (int i = 0; i < 8; i++)
        #pragma unroll
        for (int j = 0; j < 8; j++) acc[i][j] = 0.f;

    const int KT = 27;            // 26 full k-tiles + 1 partial (k0=416, 4 valid)
    float4 ra0, ra1, rb0, rb1;
    float4 z4 = make_float4(0.f, 0.f, 0.f, 0.f);

    // prologue: tile 0
    {
        int k0 = 0;
        ra0 = (k0 + kq0 < IND) ? *(const float4*)(A0 + k0 + kq0) : z4;
        ra1 = (k0 + kq1 < IND) ? *(const float4*)(A1 + k0 + kq1) : z4;
        rb0 = (k0 + kq0 < IND) ? *(const float4*)(B0 + k0 + kq0) : z4;
        rb1 = (k0 + kq1 < IND) ? *(const float4*)(B1 + k0 + kq1) : z4;
        As[0][kq0 + 0][r0] = ra0.x; As[0][kq0 + 1][r0] = ra0.y;
        As[0][kq0 + 2][r0] = ra0.z; As[0][kq0 + 3][r0] = ra0.w;
        As[0][kq1 + 0][r1] = ra1.x; As[0][kq1 + 1][r1] = ra1.y;
        As[0][kq1 + 2][r1] = ra1.z; As[0][kq1 + 3][r1] = ra1.w;
        Bs[0][kq0 + 0][r0] = rb0.x; Bs[0][kq0 + 1][r0] = rb0.y;
        Bs[0][kq0 + 2][r0] = rb0.z; Bs[0][kq0 + 3][r0] = rb0.w;
        Bs[0][kq1 + 0][r1] = rb1.x; Bs[0][kq1 + 1][r1] = rb1.y;
        Bs[0][kq1 + 2][r1] = rb1.z; Bs[0][kq1 + 3][r1] = rb1.w;
    }
    __syncthreads();

    int buf = 0;
    for (int kt = 0; kt < KT; kt++) {
        if (kt + 1 < KT) {
            int k0 = (kt + 1) * 16;
            ra0 = (k0 + kq0 < IND) ? *(const float4*)(A0 + k0 + kq0) : z4;
            ra1 = (k0 + kq1 < IND) ? *(const float4*)(A1 + k0 + kq1) : z4;
            rb0 = (k0 + kq0 < IND) ? *(const float4*)(B0 + k0 + kq0) : z4;
            rb1 = (k0 + kq1 < IND) ? *(const float4*)(B1 + k0 + kq1) : z4;
        }
        #pragma unroll
        for (int k = 0; k < 16; k++) {
            float4 a0 = *(const float4*)&As[buf][k][bq * 8];
            float4 a1 = *(const float4*)&As[buf][k][bq * 8 + 4];
            float4 bv0 = *(const float4*)&Bs[buf][k][nq * 8];
            float4 bv1 = *(const float4*)&Bs[buf][k][nq * 8 + 4];
            float am[8] = {a0.x, a0.y, a0.z, a0.w, a1.x, a1.y, a1.z, a1.w};
            float bn[8] = {bv0.x, bv0.y, bv0.z, bv0.w, bv1.x, bv1.y, bv1.z, bv1.w};
            #pragma unroll
            for (int i = 0; i < 8; i++)
                #pragma unroll
                for (int j = 0; j < 8; j++)
                    acc[i][j] += am[i] * bn[j];
        }
        if (kt + 1 < KT) {
            int nb = buf ^ 1;
            As[nb][kq0 + 0][r0] = ra0.x; As[nb][kq0 + 1][r0] = ra0.y;
            As[nb][kq0 + 2][r0] = ra0.z; As[nb][kq0 + 3][r0] = ra0.w;
            As[nb][kq1 + 0][r1] = ra1.x; As[nb][kq1 + 1][r1] = ra1.y;
            As[nb][kq1 + 2][r1] = ra1.z; As[nb][kq1 + 3][r1] = ra1.w;
            Bs[nb][kq0 + 0][r0] = rb0.x; Bs[nb][kq0 + 1][r0] = rb0.y;
            Bs[nb][kq0 + 2][r0] = rb0.z; Bs[nb][kq0 + 3][r0] = rb0.w;
            Bs[nb][kq1 + 0][r1] = rb1.x; Bs[nb][kq1 + 1][r1] = rb1.y;
            Bs[nb][kq1 + 2][r1] = rb1.z; Bs[nb][kq1 + 3][r1] = rb1.w;
            __syncthreads();
            buf = nb;
        }
    }

    // epilogue: out[((m>>6)*1024 + n)*64 + (m&63)] = acc + bias[n]
    float* out = &d_xs[dir][0][0][0];
    #pragma unroll
    for (int j = 0; j < 8; j++) {
        int n = n0 + nq * 8 + j;
        float bz = bias[n];
        #pragma unroll
        for (int i4 = 0; i4 < 8; i4 += 4) {
            int ml = bq * 8 + i4;
            int m = m0 + ml;
            int t = m >> 6, bb = m & 63;
            float4 o;
            o.x = acc[i4 + 0][j] + bz; o.y = acc[i4 + 1][j] + bz;
            o.z = acc[i4 + 2][j] + bz; o.w = acc[i4 + 3][j] + bz;
            *(float4*)&out[((size_t)t * 1024 + n) * 64 + bb] = o;
        }
    }
}

// ---------------- 4. persistent bidirectional LSTM ----------------
// 128 blocks (64/dir, 4 units each), full h_prev staged to smem each step.
// dynamic smem: Ws 4096 floats (16KB) + hsm 16384 floats (64KB) = 80KB.
__global__ void __launch_bounds__(256, 1) k_lstm(const float* __restrict__ whh_f,
                                                 const float* __restrict__ whh_b,
                                                 const int* __restrict__ lens) {
    extern __shared__ float sm[];
    float* Ws  = sm;          // [g][uj][k] -> ((g*4+uj)*256 + k)
    float* hsm = sm + 4096;   // [u][b]     -> u*64 + b
    int blk = blockIdx.x;
    int dir = blk >> 6;
    int ub  = (blk & 63) * 4;
    int tid = threadIdx.x;
    int uj  = tid >> 6;              // unit within block 0..3
    int b   = tid & 63;              // batch lane
    const float* whh = dir ? whh_b : whh_f;

    for (int i = tid; i < 4 * 4 * HH; i += 256) {
        int k = i & (HH - 1);
        int j = (i >> 8) & 3;
        int g = i >> 10;
        Ws[(g * 4 + j) * 256 + k] = whh[(size_t)(g * HH + ub + j) * HH + k];
    }
    int len_b = lens[b];
    int u = ub + uj;
    float c = 0.f, h = 0.f;
    unsigned gen = atomicAdd(&d_bg[dir], 0u);
    const float* xs_base = &d_xs[dir][0][0][0];
    float* hq_base = &d_hseq[dir][0][0][0];
    __syncthreads();

    for (int s = 0; s < TT; s++) {
        int t = dir ? (TT - 1 - s) : s;
        const float* xsp = xs_base + (size_t)t * 1024 * 64;
        float x0 = xsp[(0 * HH + u) * 64 + b];
        float x1 = xsp[(1 * HH + u) * 64 + b];
        float x2 = xsp[(2 * HH + u) * 64 + b];
        float x3 = xsp[(3 * HH + u) * 64 + b];
        float a0 = 0.f, a1 = 0.f, a2 = 0.f, a3 = 0.f;
        if (s > 0) {
            int tp = dir ? (t + 1) : (t - 1);
            const float4* hp4 = (const float4*)(hq_base + (size_t)tp * HH * BB);
            float4* hsm4 = (float4*)hsm;
            #pragma unroll
            for (int i = 0; i < 16; i++) hsm4[i * 256 + tid] = hp4[i * 256 + tid];
            __syncthreads();
            // EXACT r3 accumulation order: chunks c4=0..3, k ascending, fma tree per 4
            #pragma unroll
            for (int c4 = 0; c4 < 4; c4++) {
                const float* w0 = Ws + (0 * 4 + uj) * 256 + c4 * 64;
                const float* w1 = Ws + (1 * 4 + uj) * 256 + c4 * 64;
                const float* w2 = Ws + (2 * 4 + uj) * 256 + c4 * 64;
                const float* w3 = Ws + (3 * 4 + uj) * 256 + c4 * 64;
                const float* hc = hsm + c4 * 64 * 64;
                #pragma unroll 8
                for (int k = 0; k < 64; k += 4) {
                    float4 v0 = *(const float4*)(w0 + k);
                    float4 v1 = *(const float4*)(w1 + k);
                    float4 v2 = *(const float4*)(w2 + k);
                    float4 v3 = *(const float4*)(w3 + k);
                    float h0 = hc[k * 64 + b],       h1 = hc[(k + 1) * 64 + b];
                    float h2 = hc[(k + 2) * 64 + b], h3 = hc[(k + 3) * 64 + b];
                    a0 += h0 * v0.x + h1 * v0.y + h2 * v0.z + h3 * v0.w;
                    a1 += h0 * v1.x + h1 * v1.y + h2 * v1.z + h3 * v1.w;
                    a2 += h0 * v2.x + h1 * v2.y + h2 * v2.z + h3 * v2.w;
                    a3 += h0 * v3.x + h1 * v3.y + h2 * v3.z + h3 * v3.w;
                }
            }
        }
        float g0 = x0 + a0;
        float g1 = x1 + a1;
        float g2 = x2 + a2;
        float g3 = x3 + a3;
        float ig = 1.f / (1.f + expf(-g0));
        float fg = 1.f / (1.f + expf(-g1));
        float gg = tanhf(g2);
        float og = 1.f / (1.f + expf(-g3));
        float cn = fg * c + ig * gg;
        float hn = og * tanhf(cn);
        if (t < len_b) { c = cn; h = hn; }
        hq_base[((size_t)t * HH + u) * BB + b] = h;

        // per-direction grid barrier (generation based; survives graph replays)
        __syncthreads();
        if (tid == 0) {
            unsigned target = gen + 1;
            __threadfence();
            if (atomicAdd(&d_bc[dir], 1u) == (unsigned)(NBLK_DIR - 1)) {
                atomicExch(&d_bc[dir], 0u);
                __threadfence();
                atomicExch(&d_bg[dir], target);
            } else {
                while (*(volatile unsigned*)&d_bg[dir] != target) { }
                __threadfence();
            }
        }
        gen++;
        __syncthreads();
    }
}

// ---------------- 5. projection + mask -> feats[t][b][n] ----------------
__global__ void __launch_bounds__(256) k_proj(const float* __restrict__ proj_w,
                                              const float* __restrict__ proj_b,
                                              const int* __restrict__ lens) {
    __shared__ float hsm[64][64];
    __shared__ float pw[NT][64];
    int t = blockIdx.x;
    int tid = threadIdx.x;
    int b = tid & 63, grp = tid >> 6;      // 4 groups x 13 labels
    float acc[13];
    #pragma unroll
    for (int r = 0; r < 13; r++) acc[r] = 0.f;

    for (int kc = 0; kc < 8; kc++) {
        int u512 = kc * 64;
        int dir = u512 >> 8;
        int ubo = u512 & 255;
        const float* hp = &d_hseq[dir][t][ubo][0];
        #pragma unroll
        for (int i = 0; i < 16; i++) {
            int idx = tid + i * 256;
            hsm[idx >> 6][idx & 63] = hp[idx];
        }
        for (int i = tid; i < NT * 64; i += 256) {
            int n = i >> 6, k = i & 63;
            pw[n][k] = proj_w[(size_t)n * (2 * HH) + kc * 64 + k];
        }
        __syncthreads();
        for (int k = 0; k < 64; k++) {
            float hv = hsm[k][b];
            #pragma unroll
            for (int r = 0; r < 13; r++)
                acc[r] += hv * pw[grp * 13 + r][k];
        }
        __syncthreads();
    }
    int msk = (t < lens[b]) ? 1 : 0;
    #pragma unroll
    for (int r = 0; r < 13; r++) {
        int n = grp * 13 + r;
        d_feats[((size_t)t * 64 + b) * NT + n] = (msk ? acc[r] : 0.f) + proj_b[n];
    }
}

// ---------------- 6. CRF: forward Z + viterbi + gold + tags ----------------
__global__ void __launch_bounds__(64) k_crf(const float* __restrict__ transitions,
                                            const int* __restrict__ lens,
                                            const int* __restrict__ labels,
                                            float* __restrict__ out) {
    __shared__ float tr[NT * NT];
    __shared__ float E[NT * NT];
    __shared__ float alpha[2][64], vv[2][64], ea[64], red[64];
    __shared__ unsigned char bps[TT][NT];          // backpointers in smem
    __shared__ int s_best_last;
    int b = blockIdx.x;
    int j = threadIdx.x;

    for (int i = j; i < NT * NT; i += 64) {
        float x = transitions[i];
        tr[i] = x;
        E[i] = expf(x);                 // exp(-1e4) == 0 exactly
    }
    __syncthreads();
    int len = lens[b];

    float aj = -INFINITY;
    if (j < NT) aj = d_feats[(size_t)(0 * 64 + b) * NT + j] + tr[TSTART * NT + j];
    alpha[0][j] = aj;
    vv[0][j] = aj;
    __syncthreads();

    int p = 0;
    for (int t = 1; t < len; t++) {
        int q = p ^ 1;
        // shift by alpha[p][0] — valid logsumexp shift, no max reduction needed
        float m = alpha[p][0];
        ea[j] = (j < NT) ? expf(alpha[p][j] - m) : 0.f;
        __syncthreads();
        if (j < NT) {
            float f = d_feats[((size_t)t * 64 + b) * NT + j];
            float s = 0.f;
            #pragma unroll 4
            for (int i = 0; i < NT; i++) s += ea[i] * E[i * NT + j];
            // reference rounding order: cand = v[i] + (f[j] + T[i][j]); f INSIDE the max
            float best = -INFINITY; int bp = 0;
            for (int i = 0; i < NT; i++) {
                float sij = f + tr[i * NT + j];
                float cnd = vv[p][i] + sij;
                if (cnd > best) { best = cnd; bp = i; }
            }
            alpha[q][j] = m + logf(s) + f;
            vv[q][j] = best;
            bps[t][j] = (unsigned char)bp;
        }
        __syncthreads();
        p = q;
    }

    // ---- Z = logsumexp(alpha + tr[:,STOP]) ----
    float zx = (j < NT) ? alpha[p][j] + tr[j * NT + TSTOP] : -INFINITY;
    red[j] = zx;
    __syncthreads();
    for (int off = 32; off >= 1; off >>= 1) {
        if (j < off) red[j] = fmaxf(red[j], red[j + off]);
        __syncthreads();
    }
    float zm = red[0];
    __syncthreads();
    red[j] = (j < NT) ? expf(zx - zm) : 0.f;
    __syncthreads();
    for (int off = 32; off >= 1; off >>= 1) {
        if (j < off) red[j] += red[j + off];
        __syncthreads();
    }
    float Z = zm + logf(red[0]);
    __syncthreads();

    // ---- best last tag: exact first-index argmax (jnp.argmax semantics) ----
    red[j] = (j < NT) ? vv[p][j] + tr[j * NT + TSTOP] : -INFINITY;
    __syncthreads();
    if (j == 0) {
        float bv = -INFINITY; int bi = 0;
        for (int i = 0; i < NT; i++)
            if (red[i] > bv) { bv = red[i]; bi = i; }
        s_best_last = bi;
    }
    __syncthreads();
    int best_last = s_best_last;
    __syncthreads();

    // ---- gold score ----
    float gp = 0.f;
    for (int t = j; t < TT; t += 64) {
        if (t < len) {
            int lab = labels[b * TT + t];
            gp += d_feats[((size_t)t * 64 + b) * NT + lab];
            if (t >= 1) gp += tr[labels[b * TT + t - 1] * NT + lab];
        }
    }
    red[j] = gp;
    __syncthreads();
    for (int off = 32; off >= 1; off >>= 1) {
        if (j < off) red[j] += red[j + off];
        __syncthreads();
    }
    if (j == 0) {
        int l0 = labels[b * TT + 0];
        int ll = labels[b * TT + len - 1];
        float gold = red[0] + tr[TSTART * NT + l0] + tr[ll * NT + TSTOP];
        d_lossp[b] = Z - gold;
    }

    // ---- backtrack from smem bps + write tags ----
    if (j == 0) {
        int cur = best_last;
        for (int t = TT - 1; t >= 0; --t) {
            out[1 + b * TT + t] = (t < len) ? (float)cur : 0.f;
            if (t > 0 && t < len) cur = (int)bps[t][cur];
        }
    }
}

// ---------------- 7. loss reduction ----------------
__global__ void k_loss(float* __restrict__ out) {
    __shared__ float red[64];
    int j = threadIdx.x;
    red[j] = d_lossp[j];
    __syncthreads();
    for (int off = 32; off >= 1; off >>= 1) {
        if (j < off) red[j] += red[j + off];
        __syncthreads();
    }
    if (j == 0) out[0] = red[0];
}

// ---------------- launch ----------------
extern "C" void kernel_launch(void* const* d_in, const int* in_sizes, int n_in,
                              void* d_out, int out_size) {
    const int*   batch_word     = (const int*)  d_in[0];
    const int*   batch_features = (const int*)  d_in[1];
    const int*   batch_wordlen  = (const int*)  d_in[2];
    const int*   batch_char     = (const int*)  d_in[3];
    /* d_in[4] batch_charlen unused */
    const int*   charrecover    = (const int*)  d_in[5];
    /* d_in[6] mask unused (derived from lengths) */
    const int*   batch_label    = (const int*)  d_in[7];
    const float* char_emb       = (const float*)d_in[8];
    const float* conv_w         = (const float*)d_in[9];
    const float* conv_b         = (const float*)d_in[10];
    const float* word_emb       = (const float*)d_in[11];
    const float* feat_emb       = (const float*)d_in[12];
    const float* w_ih_f         = (const float*)d_in[13];
    const float* w_hh_f         = (const float*)d_in[14];
    const float* b_f            = (const float*)d_in[15];
    const float* w_ih_b         = (const float*)d_in[16];
    const float* w_hh_b         = (const float*)d_in[17];
    const float* b_b            = (const float*)d_in[18];
    const float* proj_w         = (const float*)d_in[19];
    const float* proj_b         = (const float*)d_in[20];
    const float* transitions    = (const float*)d_in[21];
    float* out = (float*)d_out;
    (void)in_sizes; (void)n_in; (void)out_size;

    static int smem_set = 0;
    if (!smem_set) {
        cudaFuncSetAttribute(k_lstm, cudaFuncAttributeMaxDynamicSharedMemorySize,
                             (4096 + 16384) * (int)sizeof(float));
        smem_set = 1;
    }

    k_table<<<(3 * VC * CHN + 255) / 256, 256>>>(conv_w, char_emb);
    k_build_x<<<TT * BB, 128>>>(batch_word, batch_features, batch_char,
                                charrecover, word_emb, feat_emb, conv_b);
    {
        dim3 g(128, 8, 2);        // M/128, N/128, dir
        k_gemm2<<<g, 256>>>(w_ih_f, b_f, w_ih_b, b_b);
    }
    k_lstm<<<2 * NBLK_DIR, 256, (4096 + 16384) * sizeof(float)>>>(w_hh_f, w_hh_b,
                                                                  batch_wordlen);
    k_proj<<<TT, 256>>>(proj_w, proj_b, batch_wordlen);
    k_crf<<<BB, 64>>>(transitions, batch_wordlen, batch_label, out);
    k_loss<<<1, 64>>>(out);
}

// round 5
// speedup vs baseline: 1.3628x; 1.0859x over previous
#include <cuda_runtime.h>
#include <math.h>
#include <stdint.h>

// ---------------- problem constants ----------------
#define BB 64
#define TT 256
#define LL 16
#define VC 100
#define DC 50
#define CHN 100
#define DW 300
#define DF 20
#define HH 256
#define IND 420          // DW + CHN + DF
#define NT 52            // LAB + 2
#define TSTART 50
#define TSTOP 51
#define NBLK_DIR 64      // LSTM blocks per direction

// ---------------- scratch (device globals; no allocations) ----------------
__device__ float d_tbl[3][VC][CHN];                 // conv lookup table
__device__ float d_x[(size_t)TT * BB * IND];        // x, row = t*BB + b
__device__ float d_xs[2][TT][4 * HH][BB];           // input proj, transposed [t][n][b]
__device__ float d_hseq[2][TT][HH][BB];             // per-step hidden states
__device__ float d_feats[(size_t)TT * BB * NT];     // emissions [t][b][n]
__device__ float d_lossp[BB];
__device__ unsigned d_flag[2][NBLK_DIR];            // per-block monotonic step flags

// ---------------- cp.async helpers ----------------
__device__ __forceinline__ void cp16(uint32_t dst_smem, const void* src) {
    asm volatile("cp.async.cg.shared.global [%0], [%1], 16;\n"
                 :: "r"(dst_smem), "l"(src));
}
__device__ __forceinline__ void cp_commit() {
    asm volatile("cp.async.commit_group;\n");
}
template <int N>
__device__ __forceinline__ void cp_wait() {
    asm volatile("cp.async.wait_group %0;\n" :: "n"(N));
}

// ---------------- 1. conv -> lookup table ----------------
__global__ void k_table(const float* __restrict__ conv_w,
                        const float* __restrict__ char_emb) {
    int idx = blockIdx.x * blockDim.x + threadIdx.x;
    if (idx >= 3 * VC * CHN) return;
    int ch = idx % CHN;
    int c  = (idx / CHN) % VC;
    int kk = idx / (CHN * VC);
    float s = 0.f;
    #pragma unroll 10
    for (int dc = 0; dc < DC; dc++)
        s += conv_w[(ch * DC + dc) * 3 + kk] * char_emb[c * DC + dc];
    d_tbl[kk][c][ch] = s;
}

// ---------------- 2. build x = [word_emb | char_cnn | feat_emb] ----------------
__global__ void k_build_x(const int* __restrict__ word,
                          const int* __restrict__ featidx,
                          const int* __restrict__ chars,
                          const int* __restrict__ recover,
                          const float* __restrict__ word_emb,
                          const float* __restrict__ feat_emb,
                          const float* __restrict__ conv_b) {
    int m = blockIdx.x;           // row = t*BB + b
    int t = m / BB, b = m % BB;
    int tid = threadIdx.x;
    __shared__ int cs[LL];
    float* xr = &d_x[(size_t)m * IND];
    int w = word[b * TT + t];
    const float4* we4 = (const float4*)(word_emb + (size_t)w * DW);
    float4* xr4 = (float4*)xr;
    for (int i = tid; i < DW / 4; i += blockDim.x) xr4[i] = we4[i];
    if (tid < DF) {
        int fv = featidx[b];
        xr[DW + CHN + tid] = feat_emb[fv * DF + tid];
    }
    if (tid < LL) {
        int j = recover[b * TT + t];
        cs[tid] = chars[j * LL + tid];
    }
    __syncthreads();
    if (tid < CHN) {
        float bias = conv_b[tid];
        float mx = -3.4e38f;
        #pragma unroll
        for (int l = 0; l < LL; l++) {
            float v = bias + d_tbl[1][cs[l]][tid];
            if (l > 0)       v += d_tbl[0][cs[l - 1]][tid];
            if (l < LL - 1)  v += d_tbl[2][cs[l + 1]][tid];
            mx = fmaxf(mx, v);
        }
        xr[DW + tid] = mx;
    }
}

// ---------------- 3. input projection GEMM (fused over t, both dirs) ----------------
__global__ void __launch_bounds__(256, 2) k_gemm2(const float* __restrict__ w_f,
                                                  const float* __restrict__ b_fp,
                                                  const float* __restrict__ w_b,
                                                  const float* __restrict__ b_bp) {
    __shared__ float As[2][16][128];
    __shared__ float Bs[2][16][128];
    int dir = blockIdx.z;
    const float* W    = dir ? w_b  : w_f;
    const float* bias = dir ? b_bp : b_fp;
    int m0 = blockIdx.x * 128;
    int n0 = blockIdx.y * 128;
    int tid = threadIdx.x;
    int bq = tid & 15;
    int nq = tid >> 4;

    int r0 = tid >> 2,         kq0 = (tid & 3) << 2;
    int r1 = (tid + 256) >> 2, kq1 = ((tid + 256) & 3) << 2;

    const float* A0 = &d_x[(size_t)(m0 + r0) * IND];
    const float* A1 = &d_x[(size_t)(m0 + r1) * IND];
    const float* B0 = &W[(size_t)(n0 + r0) * IND];
    const float* B1 = &W[(size_t)(n0 + r1) * IND];

    float acc[8][8];
    #pragma unroll
    for (int i = 0; i < 8; i++)
        #pragma unroll
        for (int j = 0; j < 8; j++) acc[i][j] = 0.f;

    const int KT = 27;
    float4 ra0, ra1, rb0, rb1;
    float4 z4 = make_float4(0.f, 0.f, 0.f, 0.f);

    {
        int k0 = 0;
        ra0 = (k0 + kq0 < IND) ? *(const float4*)(A0 + k0 + kq0) : z4;
        ra1 = (k0 + kq1 < IND) ? *(const float4*)(A1 + k0 + kq1) : z4;
        rb0 = (k0 + kq0 < IND) ? *(const float4*)(B0 + k0 + kq0) : z4;
        rb1 = (k0 + kq1 < IND) ? *(const float4*)(B1 + k0 + kq1) : z4;
        As[0][kq0 + 0][r0] = ra0.x; As[0][kq0 + 1][r0] = ra0.y;
        As[0][kq0 + 2][r0] = ra0.z; As[0][kq0 + 3][r0] = ra0.w;
        As[0][kq1 + 0][r1] = ra1.x; As[0][kq1 + 1][r1] = ra1.y;
        As[0][kq1 + 2][r1] = ra1.z; As[0][kq1 + 3][r1] = ra1.w;
        Bs[0][kq0 + 0][r0] = rb0.x; Bs[0][kq0 + 1][r0] = rb0.y;
        Bs[0][kq0 + 2][r0] = rb0.z; Bs[0][kq0 + 3][r0] = rb0.w;
        Bs[0][kq1 + 0][r1] = rb1.x; Bs[0][kq1 + 1][r1] = rb1.y;
        Bs[0][kq1 + 2][r1] = rb1.z; Bs[0][kq1 + 3][r1] = rb1.w;
    }
    __syncthreads();

    int buf = 0;
    for (int kt = 0; kt < KT; kt++) {
        if (kt + 1 < KT) {
            int k0 = (kt + 1) * 16;
            ra0 = (k0 + kq0 < IND) ? *(const float4*)(A0 + k0 + kq0) : z4;
            ra1 = (k0 + kq1 < IND) ? *(const float4*)(A1 + k0 + kq1) : z4;
            rb0 = (k0 + kq0 < IND) ? *(const float4*)(B0 + k0 + kq0) : z4;
            rb1 = (k0 + kq1 < IND) ? *(const float4*)(B1 + k0 + kq1) : z4;
        }
        #pragma unroll
        for (int k = 0; k < 16; k++) {
            float4 a0 = *(const float4*)&As[buf][k][bq * 8];
            float4 a1 = *(const float4*)&As[buf][k][bq * 8 + 4];
            float4 bv0 = *(const float4*)&Bs[buf][k][nq * 8];
            float4 bv1 = *(const float4*)&Bs[buf][k][nq * 8 + 4];
            float am[8] = {a0.x, a0.y, a0.z, a0.w, a1.x, a1.y, a1.z, a1.w};
            float bn[8] = {bv0.x, bv0.y, bv0.z, bv0.w, bv1.x, bv1.y, bv1.z, bv1.w};
            #pragma unroll
            for (int i = 0; i < 8; i++)
                #pragma unroll
                for (int j = 0; j < 8; j++)
                    acc[i][j] += am[i] * bn[j];
        }
        if (kt + 1 < KT) {
            int nb = buf ^ 1;
            As[nb][kq0 + 0][r0] = ra0.x; As[nb][kq0 + 1][r0] = ra0.y;
            As[nb][kq0 + 2][r0] = ra0.z; As[nb][kq0 + 3][r0] = ra0.w;
            As[nb][kq1 + 0][r1] = ra1.x; As[nb][kq1 + 1][r1] = ra1.y;
            As[nb][kq1 + 2][r1] = ra1.z; As[nb][kq1 + 3][r1] = ra1.w;
            Bs[nb][kq0 + 0][r0] = rb0.x; Bs[nb][kq0 + 1][r0] = rb0.y;
            Bs[nb][kq0 + 2][r0] = rb0.z; Bs[nb][kq0 + 3][r0] = rb0.w;
            Bs[nb][kq1 + 0][r1] = rb1.x; Bs[nb][kq1 + 1][r1] = rb1.y;
            Bs[nb][kq1 + 2][r1] = rb1.z; Bs[nb][kq1 + 3][r1] = rb1.w;
            __syncthreads();
            buf = nb;
        }
    }

    float* out = &d_xs[dir][0][0][0];
    #pragma unroll
    for (int j = 0; j < 8; j++) {
        int n = n0 + nq * 8 + j;
        float bz = bias[n];
        #pragma unroll
        for (int i4 = 0; i4 < 8; i4 += 4) {
            int ml = bq * 8 + i4;
            int m = m0 + ml;
            int t = m >> 6, bb = m & 63;
            float4 o;
            o.x = acc[i4 + 0][j] + bz; o.y = acc[i4 + 1][j] + bz;
            o.z = acc[i4 + 2][j] + bz; o.w = acc[i4 + 3][j] + bz;
            *(float4*)&out[((size_t)t * 1024 + n) * 64 + bb] = o;
        }
    }
}

// ---------------- 4. persistent bidirectional LSTM v3 ----------------
// 128 blocks (64/dir, 4 units each). Per step:
//   - prefetch x (flag-independent)
//   - parallel flag poll (thread j polls block j's flag)
//   - cp.async-staged h chunks, compute overlapped per chunk
//   - write h, fence, set own flag (contention-free)
__global__ void __launch_bounds__(256, 1) k_lstm(const float* __restrict__ whh_f,
                                                 const float* __restrict__ whh_b,
                                                 const int* __restrict__ lens) {
    extern __shared__ float sm[];
    float* Ws  = sm;          // [g][uj][k] -> ((g*4+uj)*256 + k)  16KB
    float* hsm = sm + 4096;   // [u][b]     -> u*64 + b            64KB
    int blk = blockIdx.x;
    int dir = blk >> 6;
    int f   = blk & 63;
    int ub  = f * 4;
    int tid = threadIdx.x;
    int uj  = tid >> 6;
    int b   = tid & 63;
    const float* whh = dir ? whh_b : whh_f;

    for (int i = tid; i < 4 * 4 * HH; i += 256) {
        int k = i & (HH - 1);
        int j = (i >> 8) & 3;
        int g = i >> 10;
        Ws[(g * 4 + j) * 256 + k] = whh[(size_t)(g * HH + ub + j) * HH + k];
    }
    int len_b = lens[b];
    int u = ub + uj;
    float c = 0.f, h = 0.f;
    // monotonic generation base: own flag (only this block increments it)
    unsigned gen0 = *(volatile unsigned*)&d_flag[dir][f];
    const float* xs_base = &d_xs[dir][0][0][0];
    float* hq_base = &d_hseq[dir][0][0][0];
    uint32_t hsm_s = (uint32_t)__cvta_generic_to_shared(hsm);
    volatile unsigned* flags = (volatile unsigned*)&d_flag[dir][0];
    __syncthreads();

    for (int s = 0; s < TT; s++) {
        int t = dir ? (TT - 1 - s) : s;
        const float* xsp = xs_base + (size_t)t * 1024 * 64;
        // prefetch x (independent of barrier)
        float x0 = __ldg(xsp + (0 * HH + u) * 64 + b);
        float x1 = __ldg(xsp + (1 * HH + u) * 64 + b);
        float x2 = __ldg(xsp + (2 * HH + u) * 64 + b);
        float x3 = __ldg(xsp + (3 * HH + u) * 64 + b);
        float a0 = 0.f, a1 = 0.f, a2 = 0.f, a3 = 0.f;
        if (s > 0) {
            // ---- parallel flag poll: all 64 producer blocks done with step s-1 ----
            unsigned target = gen0 + (unsigned)s;
            for (;;) {
                int ok = (tid < NBLK_DIR) ? (flags[tid] >= target) : 1;
                if (__syncthreads_and(ok)) break;
            }
            __threadfence();
            // ---- stage h via cp.async, 4 chunks of 16KB ----
            int tp = dir ? (t + 1) : (t - 1);
            const float4* hp4 = (const float4*)(hq_base + (size_t)tp * HH * BB);
            #pragma unroll
            for (int cc = 0; cc < 4; cc++) {
                #pragma unroll
                for (int i = 0; i < 4; i++) {
                    int idx = cc * 1024 + i * 256 + tid;
                    cp16(hsm_s + idx * 16, hp4 + idx);
                }
                cp_commit();
            }
            // ---- chunk-overlapped compute; EXACT r4 accumulation order ----
            #pragma unroll
            for (int c4 = 0; c4 < 4; c4++) {
                if (c4 == 0) cp_wait<3>();
                else if (c4 == 1) cp_wait<2>();
                else if (c4 == 2) cp_wait<1>();
                else cp_wait<0>();
                __syncthreads();
                const float* w0 = Ws + (0 * 4 + uj) * 256 + c4 * 64;
                const float* w1 = Ws + (1 * 4 + uj) * 256 + c4 * 64;
                const float* w2 = Ws + (2 * 4 + uj) * 256 + c4 * 64;
                const float* w3 = Ws + (3 * 4 + uj) * 256 + c4 * 64;
                const float* hc = hsm + c4 * 64 * 64;
                #pragma unroll 8
                for (int k = 0; k < 64; k += 4) {
                    float4 v0 = *(const float4*)(w0 + k);
                    float4 v1 = *(const float4*)(w1 + k);
                    float4 v2 = *(const float4*)(w2 + k);
                    float4 v3 = *(const float4*)(w3 + k);
                    float h0 = hc[k * 64 + b],       h1 = hc[(k + 1) * 64 + b];
                    float h2 = hc[(k + 2) * 64 + b], h3 = hc[(k + 3) * 64 + b];
                    a0 += h0 * v0.x + h1 * v0.y + h2 * v0.z + h3 * v0.w;
                    a1 += h0 * v1.x + h1 * v1.y + h2 * v1.z + h3 * v1.w;
                    a2 += h0 * v2.x + h1 * v2.y + h2 * v2.z + h3 * v2.w;
                    a3 += h0 * v3.x + h1 * v3.y + h2 * v3.z + h3 * v3.w;
                }
            }
        }
        float g0 = x0 + a0;
        float g1 = x1 + a1;
        float g2 = x2 + a2;
        float g3 = x3 + a3;
        float ig = 1.f / (1.f + expf(-g0));
        float fg = 1.f / (1.f + expf(-g1));
        float gg = tanhf(g2);
        float og = 1.f / (1.f + expf(-g3));
        float cn = fg * c + ig * gg;
        float hn = og * tanhf(cn);
        if (t < len_b) { c = cn; h = hn; }
        hq_base[((size_t)t * HH + u) * BB + b] = h;

        // publish: every thread fences its h store, then one thread bumps the flag
        __threadfence();
        __syncthreads();
        if (tid == 0)
            atomicExch((unsigned*)&d_flag[dir][f], gen0 + (unsigned)s + 1u);
        // no trailing sync needed: next iteration's poll re-syncs before use
    }
}

// ---------------- 5. projection + mask -> feats[t][b][n] ----------------
__global__ void __launch_bounds__(256) k_proj(const float* __restrict__ proj_w,
                                              const float* __restrict__ proj_b,
                                              const int* __restrict__ lens) {
    __shared__ float hsm[64][64];
    __shared__ float pw[NT][64];
    int t = blockIdx.x;
    int tid = threadIdx.x;
    int b = tid & 63, grp = tid >> 6;
    float acc[13];
    #pragma unroll
    for (int r = 0; r < 13; r++) acc[r] = 0.f;

    for (int kc = 0; kc < 8; kc++) {
        int u512 = kc * 64;
        int dir = u512 >> 8;
        int ubo = u512 & 255;
        const float* hp = &d_hseq[dir][t][ubo][0];
        #pragma unroll
        for (int i = 0; i < 16; i++) {
            int idx = tid + i * 256;
            hsm[idx >> 6][idx & 63] = hp[idx];
        }
        for (int i = tid; i < NT * 64; i += 256) {
            int n = i >> 6, k = i & 63;
            pw[n][k] = proj_w[(size_t)n * (2 * HH) + kc * 64 + k];
        }
        __syncthreads();
        for (int k = 0; k < 64; k++) {
            float hv = hsm[k][b];
            #pragma unroll
            for (int r = 0; r < 13; r++)
                acc[r] += hv * pw[grp * 13 + r][k];
        }
        __syncthreads();
    }
    int msk = (t < lens[b]) ? 1 : 0;
    #pragma unroll
    for (int r = 0; r < 13; r++) {
        int n = grp * 13 + r;
        d_feats[((size_t)t * 64 + b) * NT + n] = (msk ? acc[r] : 0.f) + proj_b[n];
    }
}

// ---------------- 6. CRF: forward Z + viterbi + gold + tags ----------------
__global__ void __launch_bounds__(64) k_crf(const float* __restrict__ transitions,
                                            const int* __restrict__ lens,
                                            const int* __restrict__ labels,
                                            float* __restrict__ out) {
    __shared__ float tr[NT * NT];
    __shared__ float E[NT * NT];
    __shared__ float alpha[2][64], vv[2][64], ea[64], red[64];
    __shared__ unsigned char bps[TT][NT];
    __shared__ int s_best_last;
    int b = blockIdx.x;
    int j = threadIdx.x;

    for (int i = j; i < NT * NT; i += 64) {
        float x = transitions[i];
        tr[i] = x;
        E[i] = expf(x);
    }
    __syncthreads();
    int len = lens[b];

    float aj = -INFINITY;
    if (j < NT) aj = d_feats[(size_t)(0 * 64 + b) * NT + j] + tr[TSTART * NT + j];
    alpha[0][j] = aj;
    vv[0][j] = aj;
    __syncthreads();

    int p = 0;
    for (int t = 1; t < len; t++) {
        int q = p ^ 1;
        float m = alpha[p][0];
        ea[j] = (j < NT) ? expf(alpha[p][j] - m) : 0.f;
        __syncthreads();
        if (j < NT) {
            float ff = d_feats[((size_t)t * 64 + b) * NT + j];
            float s = 0.f;
            #pragma unroll 4
            for (int i = 0; i < NT; i++) s += ea[i] * E[i * NT + j];
            float best = -INFINITY; int bp = 0;
            for (int i = 0; i < NT; i++) {
                float sij = ff + tr[i * NT + j];
                float cnd = vv[p][i] + sij;
                if (cnd > best) { best = cnd; bp = i; }
            }
            alpha[q][j] = m + logf(s) + ff;
            vv[q][j] = best;
            bps[t][j] = (unsigned char)bp;
        }
        __syncthreads();
        p = q;
    }

    float zx = (j < NT) ? alpha[p][j] + tr[j * NT + TSTOP] : -INFINITY;
    red[j] = zx;
    __syncthreads();
    for (int off = 32; off >= 1; off >>= 1) {
        if (j < off) red[j] = fmaxf(red[j], red[j + off]);
        __syncthreads();
    }
    float zm = red[0];
    __syncthreads();
    red[j] = (j < NT) ? expf(zx - zm) : 0.f;
    __syncthreads();
    for (int off = 32; off >= 1; off >>= 1) {
        if (j < off) red[j] += red[j + off];
        __syncthreads();
    }
    float Z = zm + logf(red[0]);
    __syncthreads();

    red[j] = (j < NT) ? vv[p][j] + tr[j * NT + TSTOP] : -INFINITY;
    __syncthreads();
    if (j == 0) {
        float bv = -INFINITY; int bi = 0;
        for (int i = 0; i < NT; i++)
            if (red[i] > bv) { bv = red[i]; bi = i; }
        s_best_last = bi;
    }
    __syncthreads();
    int best_last = s_best_last;
    __syncthreads();

    float gp = 0.f;
    for (int t = j; t < TT; t += 64) {
        if (t < len) {
            int lab = labels[b * TT + t];
            gp += d_feats[((size_t)t * 64 + b) * NT + lab];
            if (t >= 1) gp += tr[labels[b * TT + t - 1] * NT + lab];
        }
    }
    red[j] = gp;
    __syncthreads();
    for (int off = 32; off >= 1; off >>= 1) {
        if (j < off) red[j] += red[j + off];
        __syncthreads();
    }
    if (j == 0) {
        int l0 = labels[b * TT + 0];
        int ll = labels[b * TT + len - 1];
        float gold = red[0] + tr[TSTART * NT + l0] + tr[ll * NT + TSTOP];
        d_lossp[b] = Z - gold;
    }

    if (j == 0) {
        int cur = best_last;
        for (int t = TT - 1; t >= 0; --t) {
            out[1 + b * TT + t] = (t < len) ? (float)cur : 0.f;
            if (t > 0 && t < len) cur = (int)bps[t][cur];
        }
    }
}

// ---------------- 7. loss reduction ----------------
__global__ void k_loss(float* __restrict__ out) {
    __shared__ float red[64];
    int j = threadIdx.x;
    red[j] = d_lossp[j];
    __syncthreads();
    for (int off = 32; off >= 1; off >>= 1) {
        if (j < off) red[j] += red[j + off];
        __syncthreads();
    }
    if (j == 0) out[0] = red[0];
}

// ---------------- launch ----------------
extern "C" void kernel_launch(void* const* d_in, const int* in_sizes, int n_in,
                              void* d_out, int out_size) {
    const int*   batch_word     = (const int*)  d_in[0];
    const int*   batch_features = (const int*)  d_in[1];
    const int*   batch_wordlen  = (const int*)  d_in[2];
    const int*   batch_char     = (const int*)  d_in[3];
    const int*   charrecover    = (const int*)  d_in[5];
    const int*   batch_label    = (const int*)  d_in[7];
    const float* char_emb       = (const float*)d_in[8];
    const float* conv_w         = (const float*)d_in[9];
    const float* conv_b         = (const float*)d_in[10];
    const float* word_emb       = (const float*)d_in[11];
    const float* feat_emb       = (const float*)d_in[12];
    const float* w_ih_f         = (const float*)d_in[13];
    const float* w_hh_f         = (const float*)d_in[14];
    const float* b_f            = (const float*)d_in[15];
    const float* w_ih_b         = (const float*)d_in[16];
    const float* w_hh_b         = (const float*)d_in[17];
    const float* b_b            = (const float*)d_in[18];
    const float* proj_w         = (const float*)d_in[19];
    const float* proj_b         = (const float*)d_in[20];
    const float* transitions    = (const float*)d_in[21];
    float* out = (float*)d_out;
    (void)in_sizes; (void)n_in; (void)out_size;

    static int smem_set = 0;
    if (!smem_set) {
        cudaFuncSetAttribute(k_lstm, cudaFuncAttributeMaxDynamicSharedMemorySize,
                             (4096 + 16384) * (int)sizeof(float));
        smem_set = 1;
    }

    k_table<<<(3 * VC * CHN + 255) / 256, 256>>>(conv_w, char_emb);
    k_build_x<<<TT * BB, 128>>>(batch_word, batch_features, batch_char,
                                charrecover, word_emb, feat_emb, conv_b);
    {
        dim3 g(128, 8, 2);
        k_gemm2<<<g, 256>>>(w_ih_f, b_f, w_ih_b, b_b);
    }
    k_lstm<<<2 * NBLK_DIR, 256, (4096 + 16384) * sizeof(float)>>>(w_hh_f, w_hh_b,
                                                                  batch_wordlen);
    k_proj<<<TT, 256>>>(proj_w, proj_b, batch_wordlen);
    k_crf<<<BB, 64>>>(transitions, batch_wordlen, batch_label, out);
    k_loss<<<1, 64>>>(out);
}

// round 6
// speedup vs baseline: 1.3640x; 1.0009x over previous
#include <cuda_runtime.h>
#include <math.h>
#include <stdint.h>
#include <string.h>

// ---------------- problem constants ----------------
#define BB 64
#define TT 256
#define LL 16
#define VC 100
#define DC 50
#define CHN 100
#define DW 300
#define DF 20
#define HH 256
#define IND 420          // DW + CHN + DF
#define NT 52            // LAB + 2
#define TSTART 50
#define TSTOP 51
#define NBLK_DIR 64      // LSTM blocks per direction

typedef unsigned long long ull;

// ---------------- scratch (device globals; no allocations) ----------------
__device__ float d_tbl[3][VC][CHN];                 // conv lookup table
__device__ float d_x[(size_t)TT * BB * IND];        // x, row = t*BB + b
__device__ float d_xs[2][TT][4 * HH][BB];           // input proj, transposed [t][n][b]
__device__ float d_hseq[2][TT][HH][BB];             // per-step hidden states
__device__ float d_feats[(size_t)TT * BB * NT];     // emissions [t][b][n]
__device__ float d_lossp[BB];
__device__ unsigned d_flag[2][NBLK_DIR];            // per-block monotonic step flags

// ---------------- helpers ----------------
__device__ __forceinline__ void cp16(uint32_t dst_smem, const void* src) {
    asm volatile("cp.async.cg.shared.global [%0], [%1], 16;\n"
                 :: "r"(dst_smem), "l"(src));
}
__device__ __forceinline__ void cp_commit() {
    asm volatile("cp.async.commit_group;\n");
}
template <int N>
__device__ __forceinline__ void cp_wait() {
    asm volatile("cp.async.wait_group %0;\n" :: "n"(N));
}
// packed dual fp32 fma: per-lane IEEE fp32, same rounding as scalar fmaf
__device__ __forceinline__ ull fma2(ull h, ull w, ull acc) {
    ull d;
    asm("fma.rn.f32x2 %0, %1, %2, %3;" : "=l"(d) : "l"(h), "l"(w), "l"(acc));
    return d;
}

// ---------------- 1. conv -> lookup table ----------------
__global__ void k_table(const float* __restrict__ conv_w,
                        const float* __restrict__ char_emb) {
    int idx = blockIdx.x * blockDim.x + threadIdx.x;
    if (idx >= 3 * VC * CHN) return;
    int ch = idx % CHN;
    int c  = (idx / CHN) % VC;
    int kk = idx / (CHN * VC);
    float s = 0.f;
    #pragma unroll 10
    for (int dc = 0; dc < DC; dc++)
        s += conv_w[(ch * DC + dc) * 3 + kk] * char_emb[c * DC + dc];
    d_tbl[kk][c][ch] = s;
}

// ---------------- 2. build x = [word_emb | char_cnn | feat_emb] ----------------
__global__ void k_build_x(const int* __restrict__ word,
                          const int* __restrict__ featidx,
                          const int* __restrict__ chars,
                          const int* __restrict__ recover,
                          const float* __restrict__ word_emb,
                          const float* __restrict__ feat_emb,
                          const float* __restrict__ conv_b) {
    int m = blockIdx.x;           // row = t*BB + b
    int t = m / BB, b = m % BB;
    int tid = threadIdx.x;
    __shared__ int cs[LL];
    float* xr = &d_x[(size_t)m * IND];
    int w = word[b * TT + t];
    const float4* we4 = (const float4*)(word_emb + (size_t)w * DW);
    float4* xr4 = (float4*)xr;
    for (int i = tid; i < DW / 4; i += blockDim.x) xr4[i] = we4[i];
    if (tid < DF) {
        int fv = featidx[b];
        xr[DW + CHN + tid] = feat_emb[fv * DF + tid];
    }
    if (tid < LL) {
        int j = recover[b * TT + t];
        cs[tid] = chars[j * LL + tid];
    }
    __syncthreads();
    if (tid < CHN) {
        float bias = conv_b[tid];
        float mx = -3.4e38f;
        #pragma unroll
        for (int l = 0; l < LL; l++) {
            float v = bias + d_tbl[1][cs[l]][tid];
            if (l > 0)       v += d_tbl[0][cs[l - 1]][tid];
            if (l < LL - 1)  v += d_tbl[2][cs[l + 1]][tid];
            mx = fmaxf(mx, v);
        }
        xr[DW + tid] = mx;
    }
}

// ---------------- 3. input projection GEMM (fused over t, both dirs) ----------------
__global__ void __launch_bounds__(256, 2) k_gemm2(const float* __restrict__ w_f,
                                                  const float* __restrict__ b_fp,
                                                  const float* __restrict__ w_b,
                                                  const float* __restrict__ b_bp) {
    __shared__ float As[2][16][128];
    __shared__ float Bs[2][16][128];
    int dir = blockIdx.z;
    const float* W    = dir ? w_b  : w_f;
    const float* bias = dir ? b_bp : b_fp;
    int m0 = blockIdx.x * 128;
    int n0 = blockIdx.y * 128;
    int tid = threadIdx.x;
    int bq = tid & 15;
    int nq = tid >> 4;

    int r0 = tid >> 2,         kq0 = (tid & 3) << 2;
    int r1 = (tid + 256) >> 2, kq1 = ((tid + 256) & 3) << 2;

    const float* A0 = &d_x[(size_t)(m0 + r0) * IND];
    const float* A1 = &d_x[(size_t)(m0 + r1) * IND];
    const float* B0 = &W[(size_t)(n0 + r0) * IND];
    const float* B1 = &W[(size_t)(n0 + r1) * IND];

    float acc[8][8];
    #pragma unroll
    for (int i = 0; i < 8; i++)
        #pragma unroll
        for (int j = 0; j < 8; j++) acc[i][j] = 0.f;

    const int KT = 27;
    float4 ra0, ra1, rb0, rb1;
    float4 z4 = make_float4(0.f, 0.f, 0.f, 0.f);

    {
        int k0 = 0;
        ra0 = (k0 + kq0 < IND) ? *(const float4*)(A0 + k0 + kq0) : z4;
        ra1 = (k0 + kq1 < IND) ? *(const float4*)(A1 + k0 + kq1) : z4;
        rb0 = (k0 + kq0 < IND) ? *(const float4*)(B0 + k0 + kq0) : z4;
        rb1 = (k0 + kq1 < IND) ? *(const float4*)(B1 + k0 + kq1) : z4;
        As[0][kq0 + 0][r0] = ra0.x; As[0][kq0 + 1][r0] = ra0.y;
        As[0][kq0 + 2][r0] = ra0.z; As[0][kq0 + 3][r0] = ra0.w;
        As[0][kq1 + 0][r1] = ra1.x; As[0][kq1 + 1][r1] = ra1.y;
        As[0][kq1 + 2][r1] = ra1.z; As[0][kq1 + 3][r1] = ra1.w;
        Bs[0][kq0 + 0][r0] = rb0.x; Bs[0][kq0 + 1][r0] = rb0.y;
        Bs[0][kq0 + 2][r0] = rb0.z; Bs[0][kq0 + 3][r0] = rb0.w;
        Bs[0][kq1 + 0][r1] = rb1.x; Bs[0][kq1 + 1][r1] = rb1.y;
        Bs[0][kq1 + 2][r1] = rb1.z; Bs[0][kq1 + 3][r1] = rb1.w;
    }
    __syncthreads();

    int buf = 0;
    for (int kt = 0; kt < KT; kt++) {
        if (kt + 1 < KT) {
            int k0 = (kt + 1) * 16;
            ra0 = (k0 + kq0 < IND) ? *(const float4*)(A0 + k0 + kq0) : z4;
            ra1 = (k0 + kq1 < IND) ? *(const float4*)(A1 + k0 + kq1) : z4;
            rb0 = (k0 + kq0 < IND) ? *(const float4*)(B0 + k0 + kq0) : z4;
            rb1 = (k0 + kq1 < IND) ? *(const float4*)(B1 + k0 + kq1) : z4;
        }
        #pragma unroll
        for (int k = 0; k < 16; k++) {
            float4 a0 = *(const float4*)&As[buf][k][bq * 8];
            float4 a1 = *(const float4*)&As[buf][k][bq * 8 + 4];
            float4 bv0 = *(const float4*)&Bs[buf][k][nq * 8];
            float4 bv1 = *(const float4*)&Bs[buf][k][nq * 8 + 4];
            float am[8] = {a0.x, a0.y, a0.z, a0.w, a1.x, a1.y, a1.z, a1.w};
            float bn[8] = {bv0.x, bv0.y, bv0.z, bv0.w, bv1.x, bv1.y, bv1.z, bv1.w};
            #pragma unroll
            for (int i = 0; i < 8; i++)
                #pragma unroll
                for (int j = 0; j < 8; j++)
                    acc[i][j] += am[i] * bn[j];
        }
        if (kt + 1 < KT) {
            int nb = buf ^ 1;
            As[nb][kq0 + 0][r0] = ra0.x; As[nb][kq0 + 1][r0] = ra0.y;
            As[nb][kq0 + 2][r0] = ra0.z; As[nb][kq0 + 3][r0] = ra0.w;
            As[nb][kq1 + 0][r1] = ra1.x; As[nb][kq1 + 1][r1] = ra1.y;
            As[nb][kq1 + 2][r1] = ra1.z; As[nb][kq1 + 3][r1] = ra1.w;
            Bs[nb][kq0 + 0][r0] = rb0.x; Bs[nb][kq0 + 1][r0] = rb0.y;
            Bs[nb][kq0 + 2][r0] = rb0.z; Bs[nb][kq0 + 3][r0] = rb0.w;
            Bs[nb][kq1 + 0][r1] = rb1.x; Bs[nb][kq1 + 1][r1] = rb1.y;
            Bs[nb][kq1 + 2][r1] = rb1.z; Bs[nb][kq1 + 3][r1] = rb1.w;
            __syncthreads();
            buf = nb;
        }
    }

    float* out = &d_xs[dir][0][0][0];
    #pragma unroll
    for (int j = 0; j < 8; j++) {
        int n = n0 + nq * 8 + j;
        float bz = bias[n];
        #pragma unroll
        for (int i4 = 0; i4 < 8; i4 += 4) {
            int ml = bq * 8 + i4;
            int m = m0 + ml;
            int t = m >> 6, bb = m & 63;
            float4 o;
            o.x = acc[i4 + 0][j] + bz; o.y = acc[i4 + 1][j] + bz;
            o.z = acc[i4 + 2][j] + bz; o.w = acc[i4 + 3][j] + bz;
            *(float4*)&out[((size_t)t * 1024 + n) * 64 + bb] = o;
        }
    }
}

// ---------------- 4. persistent bidirectional LSTM v4 (FFMA2) ----------------
// 128 blocks (64/dir), 128 threads: uj = tid>>5 (4 units), bp = tid&31
// (sample pair 2bp, 2bp+1 packed in f32x2). Weights duplicated in smem so
// LDS.128 yields {w,w},{w',w'} FFMA2 operands. Bit-exact vs scalar version.
__global__ void __launch_bounds__(128, 1) k_lstm(const float* __restrict__ whh_f,
                                                 const float* __restrict__ whh_b,
                                                 const int* __restrict__ lens) {
    extern __shared__ float sm[];
    float* Ws2 = sm;          // dup pairs: ull index (g*4+uj)*256 + k   32KB
    float* hsm = sm + 8192;   // [k][b] floats                          64KB
    int blk = blockIdx.x;
    int dir = blk >> 6;
    int f   = blk & 63;
    int ub  = f * 4;
    int tid = threadIdx.x;
    int uj  = tid >> 5;              // unit 0..3
    int bp  = tid & 31;              // sample pair 0..31
    const float* whh = dir ? whh_b : whh_f;

    for (int i = tid; i < 4 * 4 * HH; i += 128) {
        int k = i & (HH - 1);
        int j = (i >> 8) & 3;
        int g = i >> 10;
        float w = whh[(size_t)(g * HH + ub + j) * HH + k];
        Ws2[2 * i]     = w;
        Ws2[2 * i + 1] = w;
    }
    int len0 = lens[2 * bp];
    int len1 = lens[2 * bp + 1];
    int u = ub + uj;
    float c0 = 0.f, h0v = 0.f, c1 = 0.f, h1v = 0.f;
    unsigned gen0 = *(volatile unsigned*)&d_flag[dir][f];
    const float* xs_base = &d_xs[dir][0][0][0];
    float* hq_base = &d_hseq[dir][0][0][0];
    uint32_t hsm_s = (uint32_t)__cvta_generic_to_shared(hsm);
    volatile unsigned* flags = (volatile unsigned*)&d_flag[dir][0];
    const ull* W2 = (const ull*)Ws2;
    __syncthreads();

    for (int s = 0; s < TT; s++) {
        int t = dir ? (TT - 1 - s) : s;
        const float* xsp = xs_base + (size_t)t * 1024 * 64;
        // prefetch gate inputs (flag-independent)
        float2 x0 = *(const float2*)(xsp + (0 * HH + u) * 64 + 2 * bp);
        float2 x1 = *(const float2*)(xsp + (1 * HH + u) * 64 + 2 * bp);
        float2 x2 = *(const float2*)(xsp + (2 * HH + u) * 64 + 2 * bp);
        float2 x3 = *(const float2*)(xsp + (3 * HH + u) * 64 + 2 * bp);
        ull a0 = 0ull, a1 = 0ull, a2 = 0ull, a3 = 0ull;
        if (s > 0) {
            // parallel flag poll: all 64 producer blocks done with step s-1
            unsigned target = gen0 + (unsigned)s;
            for (;;) {
                int ok = (tid < NBLK_DIR) ? (flags[tid] >= target) : 1;
                if (__syncthreads_and(ok)) break;
            }
            __threadfence();   // acquire side; no pending stores -> cheap
            // stage h via cp.async, 4 chunks of 16KB (k-ranges match compute)
            int tp = dir ? (t + 1) : (t - 1);
            const float4* hp4 = (const float4*)(hq_base + (size_t)tp * HH * BB);
            #pragma unroll
            for (int cc = 0; cc < 4; cc++) {
                #pragma unroll
                for (int i = 0; i < 8; i++) {
                    int idx = cc * 1024 + i * 128 + tid;
                    cp16(hsm_s + idx * 16, hp4 + idx);
                }
                cp_commit();
            }
            const ull* H2 = (const ull*)hsm;
            // chunk-overlapped compute; per-sample fma chain identical to scalar
            #pragma unroll
            for (int c4 = 0; c4 < 4; c4++) {
                if (c4 == 0) cp_wait<3>();
                else if (c4 == 1) cp_wait<2>();
                else if (c4 == 2) cp_wait<1>();
                else cp_wait<0>();
                __syncthreads();
                const ull* w0 = W2 + (0 * 4 + uj) * 256 + c4 * 64;
                const ull* w1 = W2 + (1 * 4 + uj) * 256 + c4 * 64;
                const ull* w2 = W2 + (2 * 4 + uj) * 256 + c4 * 64;
                const ull* w3 = W2 + (3 * 4 + uj) * 256 + c4 * 64;
                const ull* hc = H2 + c4 * 64 * 32;
                #pragma unroll 8
                for (int k = 0; k < 64; k += 4) {
                    ull hk0 = hc[(k + 0) * 32 + bp];
                    ull hk1 = hc[(k + 1) * 32 + bp];
                    ull hk2 = hc[(k + 2) * 32 + bp];
                    ull hk3 = hc[(k + 3) * 32 + bp];
                    ulonglong2 p0a = *(const ulonglong2*)(w0 + k);
                    ulonglong2 p0b = *(const ulonglong2*)(w0 + k + 2);
                    ulonglong2 p1a = *(const ulonglong2*)(w1 + k);
                    ulonglong2 p1b = *(const ulonglong2*)(w1 + k + 2);
                    ulonglong2 p2a = *(const ulonglong2*)(w2 + k);
                    ulonglong2 p2b = *(const ulonglong2*)(w2 + k + 2);
                    ulonglong2 p3a = *(const ulonglong2*)(w3 + k);
                    ulonglong2 p3b = *(const ulonglong2*)(w3 + k + 2);
                    a0 = fma2(hk0, p0a.x, a0); a0 = fma2(hk1, p0a.y, a0);
                    a0 = fma2(hk2, p0b.x, a0); a0 = fma2(hk3, p0b.y, a0);
                    a1 = fma2(hk0, p1a.x, a1); a1 = fma2(hk1, p1a.y, a1);
                    a1 = fma2(hk2, p1b.x, a1); a1 = fma2(hk3, p1b.y, a1);
                    a2 = fma2(hk0, p2a.x, a2); a2 = fma2(hk1, p2a.y, a2);
                    a2 = fma2(hk2, p2b.x, a2); a2 = fma2(hk3, p2b.y, a2);
                    a3 = fma2(hk0, p3a.x, a3); a3 = fma2(hk1, p3a.y, a3);
                    a3 = fma2(hk2, p3b.x, a3); a3 = fma2(hk3, p3b.y, a3);
                }
            }
        }
        float2 av0, av1, av2, av3;
        memcpy(&av0, &a0, 8); memcpy(&av1, &a1, 8);
        memcpy(&av2, &a2, 8); memcpy(&av3, &a3, 8);
        // sample 0
        {
            float g0 = x0.x + av0.x, g1 = x1.x + av1.x;
            float g2 = x2.x + av2.x, g3 = x3.x + av3.x;
            float ig = 1.f / (1.f + expf(-g0));
            float fg = 1.f / (1.f + expf(-g1));
            float gg = tanhf(g2);
            float og = 1.f / (1.f + expf(-g3));
            float cn = fg * c0 + ig * gg;
            float hn = og * tanhf(cn);
            if (t < len0) { c0 = cn; h0v = hn; }
        }
        // sample 1
        {
            float g0 = x0.y + av0.y, g1 = x1.y + av1.y;
            float g2 = x2.y + av2.y, g3 = x3.y + av3.y;
            float ig = 1.f / (1.f + expf(-g0));
            float fg = 1.f / (1.f + expf(-g1));
            float gg = tanhf(g2);
            float og = 1.f / (1.f + expf(-g3));
            float cn = fg * c1 + ig * gg;
            float hn = og * tanhf(cn);
            if (t < len1) { c1 = cn; h1v = hn; }
        }
        float2 hw; hw.x = h0v; hw.y = h1v;
        *(float2*)(hq_base + ((size_t)t * HH + u) * BB + 2 * bp) = hw;

        // publish: CG-style release — one fence + flag bump by thread 0
        __syncthreads();
        if (tid == 0) {
            __threadfence();
            atomicExch((unsigned*)&d_flag[dir][f], gen0 + (unsigned)s + 1u);
        }
    }
}

// ---------------- 5. projection + mask -> feats[t][b][n] ----------------
__global__ void __launch_bounds__(256) k_proj(const float* __restrict__ proj_w,
                                              const float* __restrict__ proj_b,
                                              const int* __restrict__ lens) {
    __shared__ float hsm[64][64];
    __shared__ float pw[NT][64];
    int t = blockIdx.x;
    int tid = threadIdx.x;
    int b = tid & 63, grp = tid >> 6;
    float acc[13];
    #pragma unroll
    for (int r = 0; r < 13; r++) acc[r] = 0.f;

    for (int kc = 0; kc < 8; kc++) {
        int u512 = kc * 64;
        int dir = u512 >> 8;
        int ubo = u512 & 255;
        const float* hp = &d_hseq[dir][t][ubo][0];
        #pragma unroll
        for (int i = 0; i < 16; i++) {
            int idx = tid + i * 256;
            hsm[idx >> 6][idx & 63] = hp[idx];
        }
        for (int i = tid; i < NT * 64; i += 256) {
            int n = i >> 6, k = i & 63;
            pw[n][k] = proj_w[(size_t)n * (2 * HH) + kc * 64 + k];
        }
        __syncthreads();
        for (int k = 0; k < 64; k++) {
            float hv = hsm[k][b];
            #pragma unroll
            for (int r = 0; r < 13; r++)
                acc[r] += hv * pw[grp * 13 + r][k];
        }
        __syncthreads();
    }
    int msk = (t < lens[b]) ? 1 : 0;
    #pragma unroll
    for (int r = 0; r < 13; r++) {
        int n = grp * 13 + r;
        d_feats[((size_t)t * 64 + b) * NT + n] = (msk ? acc[r] : 0.f) + proj_b[n];
    }
}

// ---------------- 6. CRF: forward Z + viterbi + gold + tags ----------------
__global__ void __launch_bounds__(64) k_crf(const float* __restrict__ transitions,
                                            const int* __restrict__ lens,
                                            const int* __restrict__ labels,
                                            float* __restrict__ out) {
    __shared__ float tr[NT * NT];
    __shared__ float E[NT * NT];
    __shared__ float alpha[2][64], vv[2][64], ea[64], red[64];
    __shared__ unsigned char bps[TT][NT];
    __shared__ int s_best_last;
    int b = blockIdx.x;
    int j = threadIdx.x;

    for (int i = j; i < NT * NT; i += 64) {
        float x = transitions[i];
        tr[i] = x;
        E[i] = expf(x);
    }
    __syncthreads();
    int len = lens[b];

    float aj = -INFINITY;
    if (j < NT) aj = d_feats[(size_t)(0 * 64 + b) * NT + j] + tr[TSTART * NT + j];
    alpha[0][j] = aj;
    vv[0][j] = aj;
    __syncthreads();

    int p = 0;
    for (int t = 1; t < len; t++) {
        int q = p ^ 1;
        float m = alpha[p][0];
        ea[j] = (j < NT) ? expf(alpha[p][j] - m) : 0.f;
        __syncthreads();
        if (j < NT) {
            float ff = d_feats[((size_t)t * 64 + b) * NT + j];
            float s = 0.f;
            #pragma unroll 4
            for (int i = 0; i < NT; i++) s += ea[i] * E[i * NT + j];
            float best = -INFINITY; int bp = 0;
            for (int i = 0; i < NT; i++) {
                float sij = ff + tr[i * NT + j];
                float cnd = vv[p][i] + sij;
                if (cnd > best) { best = cnd; bp = i; }
            }
            alpha[q][j] = m + logf(s) + ff;
            vv[q][j] = best;
            bps[t][j] = (unsigned char)bp;
        }
        __syncthreads();
        p = q;
    }

    float zx = (j < NT) ? alpha[p][j] + tr[j * NT + TSTOP] : -INFINITY;
    red[j] = zx;
    __syncthreads();
    for (int off = 32; off >= 1; off >>= 1) {
        if (j < off) red[j] = fmaxf(red[j], red[j + off]);
        __syncthreads();
    }
    float zm = red[0];
    __syncthreads();
    red[j] = (j < NT) ? expf(zx - zm) : 0.f;
    __syncthreads();
    for (int off = 32; off >= 1; off >>= 1) {
        if (j < off) red[j] += red[j + off];
        __syncthreads();
    }
    float Z = zm + logf(red[0]);
    __syncthreads();

    red[j] = (j < NT) ? vv[p][j] + tr[j * NT + TSTOP] : -INFINITY;
    __syncthreads();
    if (j == 0) {
        float bv = -INFINITY; int bi = 0;
        for (int i = 0; i < NT; i++)
            if (red[i] > bv) { bv = red[i]; bi = i; }
        s_best_last = bi;
    }
    __syncthreads();
    int best_last = s_best_last;
    __syncthreads();

    float gp = 0.f;
    for (int t = j; t < TT; t += 64) {
        if (t < len) {
            int lab = labels[b * TT + t];
            gp += d_feats[((size_t)t * 64 + b) * NT + lab];
            if (t >= 1) gp += tr[labels[b * TT + t - 1] * NT + lab];
        }
    }
    red[j] = gp;
    __syncthreads();
    for (int off = 32; off >= 1; off >>= 1) {
        if (j < off) red[j] += red[j + off];
        __syncthreads();
    }
    if (j == 0) {
        int l0 = labels[b * TT + 0];
        int ll = labels[b * TT + len - 1];
        float gold = red[0] + tr[TSTART * NT + l0] + tr[ll * NT + TSTOP];
        d_lossp[b] = Z - gold;
    }

    if (j == 0) {
        int cur = best_last;
        for (int t = TT - 1; t >= 0; --t) {
            out[1 + b * TT + t] = (t < len) ? (float)cur : 0.f;
            if (t > 0 && t < len) cur = (int)bps[t][cur];
        }
    }
}

// ---------------- 7. loss reduction ----------------
__global__ void k_loss(float* __restrict__ out) {
    __shared__ float red[64];
    int j = threadIdx.x;
    red[j] = d_lossp[j];
    __syncthreads();
    for (int off = 32; off >= 1; off >>= 1) {
        if (j < off) red[j] += red[j + off];
        __syncthreads();
    }
    if (j == 0) out[0] = red[0];
}

// ---------------- launch ----------------
extern "C" void kernel_launch(void* const* d_in, const int* in_sizes, int n_in,
                              void* d_out, int out_size) {
    const int*   batch_word     = (const int*)  d_in[0];
    const int*   batch_features = (const int*)  d_in[1];
    const int*   batch_wordlen  = (const int*)  d_in[2];
    const int*   batch_char     = (const int*)  d_in[3];
    const int*   charrecover    = (const int*)  d_in[5];
    const int*   batch_label    = (const int*)  d_in[7];
    const float* char_emb       = (const float*)d_in[8];
    const float* conv_w         = (const float*)d_in[9];
    const float* conv_b         = (const float*)d_in[10];
    const float* word_emb       = (const float*)d_in[11];
    const float* feat_emb       = (const float*)d_in[12];
    const float* w_ih_f         = (const float*)d_in[13];
    const float* w_hh_f         = (const float*)d_in[14];
    const float* b_f            = (const float*)d_in[15];
    const float* w_ih_b         = (const float*)d_in[16];
    const float* w_hh_b         = (const float*)d_in[17];
    const float* b_b            = (const float*)d_in[18];
    const float* proj_w         = (const float*)d_in[19];
    const float* proj_b         = (const float*)d_in[20];
    const float* transitions    = (const float*)d_in[21];
    float* out = (float*)d_out;
    (void)in_sizes; (void)n_in; (void)out_size;

    static int smem_set = 0;
    if (!smem_set) {
        cudaFuncSetAttribute(k_lstm, cudaFuncAttributeMaxDynamicSharedMemorySize,
                             (8192 + 16384) * (int)sizeof(float));
        smem_set = 1;
    }

    k_table<<<(3 * VC * CHN + 255) / 256, 256>>>(conv_w, char_emb);
    k_build_x<<<TT * BB, 128>>>(batch_word, batch_features, batch_char,
                                charrecover, word_emb, feat_emb, conv_b);
    {
        dim3 g(128, 8, 2);
        k_gemm2<<<g, 256>>>(w_ih_f, b_f, w_ih_b, b_b);
    }
    k_lstm<<<2 * NBLK_DIR, 128, (8192 + 16384) * sizeof(float)>>>(w_hh_f, w_hh_b,
                                                                  batch_wordlen);
    k_proj<<<TT, 256>>>(proj_w, proj_b, batch_wordlen);
    k_crf<<<BB, 64>>>(transitions, batch_wordlen, batch_label, out);
    k_loss<<<1, 64>>>(out);
}

// round 7
// speedup vs baseline: 1.4161x; 1.0382x over previous
#include <cuda_runtime.h>
#include <math.h>
#include <stdint.h>
#include <string.h>

// ---------------- problem constants ----------------
#define BB 64
#define TT 256
#define LL 16
#define VC 100
#define DC 50
#define CHN 100
#define DW 300
#define DF 20
#define HH 256
#define IND 420          // DW + CHN + DF
#define NT 52            // LAB + 2
#define TSTART 50
#define TSTOP 51
#define NBLK_DIR 64      // LSTM blocks per direction

typedef unsigned long long ull;

// ---------------- scratch (device globals; no allocations) ----------------
__device__ float d_tbl[3][VC][CHN];                 // conv lookup table
__device__ float d_x[(size_t)TT * BB * IND];        // x, row = t*BB + b
__device__ float d_xs[2][TT][4 * HH][BB];           // input proj, transposed [t][n][b]
__device__ float d_hseq[2][TT][HH][BB];             // per-step hidden states
__device__ float d_feats[(size_t)TT * BB * NT];     // emissions [t][b][n]
__device__ float d_lossp[BB];
__device__ unsigned d_flag[2][NBLK_DIR];            // per-block monotonic step flags

// ---------------- helpers ----------------
__device__ __forceinline__ void cp16(uint32_t dst_smem, const void* src) {
    asm volatile("cp.async.cg.shared.global [%0], [%1], 16;\n"
                 :: "r"(dst_smem), "l"(src));
}
__device__ __forceinline__ void cp_commit() {
    asm volatile("cp.async.commit_group;\n");
}
template <int N>
__device__ __forceinline__ void cp_wait() {
    asm volatile("cp.async.wait_group %0;\n" :: "n"(N));
}
// packed dual fp32 fma: per-lane IEEE fp32, same rounding as scalar fmaf
__device__ __forceinline__ ull fma2(ull h, ull w, ull acc) {
    ull d;
    asm("fma.rn.f32x2 %0, %1, %2, %3;" : "=l"(d) : "l"(h), "l"(w), "l"(acc));
    return d;
}

// ---------------- 1. conv -> lookup table ----------------
__global__ void k_table(const float* __restrict__ conv_w,
                        const float* __restrict__ char_emb) {
    int idx = blockIdx.x * blockDim.x + threadIdx.x;
    if (idx >= 3 * VC * CHN) return;
    int ch = idx % CHN;
    int c  = (idx / CHN) % VC;
    int kk = idx / (CHN * VC);
    float s = 0.f;
    #pragma unroll 10
    for (int dc = 0; dc < DC; dc++)
        s += conv_w[(ch * DC + dc) * 3 + kk] * char_emb[c * DC + dc];
    d_tbl[kk][c][ch] = s;
}

// ---------------- 2. build x = [word_emb | char_cnn | feat_emb] ----------------
__global__ void k_build_x(const int* __restrict__ word,
                          const int* __restrict__ featidx,
                          const int* __restrict__ chars,
                          const int* __restrict__ recover,
                          const float* __restrict__ word_emb,
                          const float* __restrict__ feat_emb,
                          const float* __restrict__ conv_b) {
    int m = blockIdx.x;           // row = t*BB + b
    int t = m / BB, b = m % BB;
    int tid = threadIdx.x;
    __shared__ int cs[LL];
    float* xr = &d_x[(size_t)m * IND];
    int w = word[b * TT + t];
    const float4* we4 = (const float4*)(word_emb + (size_t)w * DW);
    float4* xr4 = (float4*)xr;
    for (int i = tid; i < DW / 4; i += blockDim.x) xr4[i] = we4[i];
    if (tid < DF) {
        int fv = featidx[b];
        xr[DW + CHN + tid] = feat_emb[fv * DF + tid];
    }
    if (tid < LL) {
        int j = recover[b * TT + t];
        cs[tid] = chars[j * LL + tid];
    }
    __syncthreads();
    if (tid < CHN) {
        float bias = conv_b[tid];
        float mx = -3.4e38f;
        #pragma unroll
        for (int l = 0; l < LL; l++) {
            float v = bias + d_tbl[1][cs[l]][tid];
            if (l > 0)       v += d_tbl[0][cs[l - 1]][tid];
            if (l < LL - 1)  v += d_tbl[2][cs[l + 1]][tid];
            mx = fmaxf(mx, v);
        }
        xr[DW + tid] = mx;
    }
}

// ---------------- 3. input projection GEMM (fused over t, both dirs) ----------------
__global__ void __launch_bounds__(256, 2) k_gemm2(const float* __restrict__ w_f,
                                                  const float* __restrict__ b_fp,
                                                  const float* __restrict__ w_b,
                                                  const float* __restrict__ b_bp) {
    __shared__ float As[2][16][128];
    __shared__ float Bs[2][16][128];
    int dir = blockIdx.z;
    const float* W    = dir ? w_b  : w_f;
    const float* bias = dir ? b_bp : b_fp;
    int m0 = blockIdx.x * 128;
    int n0 = blockIdx.y * 128;
    int tid = threadIdx.x;
    int bq = tid & 15;
    int nq = tid >> 4;

    int r0 = tid >> 2,         kq0 = (tid & 3) << 2;
    int r1 = (tid + 256) >> 2, kq1 = ((tid + 256) & 3) << 2;

    const float* A0 = &d_x[(size_t)(m0 + r0) * IND];
    const float* A1 = &d_x[(size_t)(m0 + r1) * IND];
    const float* B0 = &W[(size_t)(n0 + r0) * IND];
    const float* B1 = &W[(size_t)(n0 + r1) * IND];

    float acc[8][8];
    #pragma unroll
    for (int i = 0; i < 8; i++)
        #pragma unroll
        for (int j = 0; j < 8; j++) acc[i][j] = 0.f;

    const int KT = 27;
    float4 ra0, ra1, rb0, rb1;
    float4 z4 = make_float4(0.f, 0.f, 0.f, 0.f);

    {
        int k0 = 0;
        ra0 = (k0 + kq0 < IND) ? *(const float4*)(A0 + k0 + kq0) : z4;
        ra1 = (k0 + kq1 < IND) ? *(const float4*)(A1 + k0 + kq1) : z4;
        rb0 = (k0 + kq0 < IND) ? *(const float4*)(B0 + k0 + kq0) : z4;
        rb1 = (k0 + kq1 < IND) ? *(const float4*)(B1 + k0 + kq1) : z4;
        As[0][kq0 + 0][r0] = ra0.x; As[0][kq0 + 1][r0] = ra0.y;
        As[0][kq0 + 2][r0] = ra0.z; As[0][kq0 + 3][r0] = ra0.w;
        As[0][kq1 + 0][r1] = ra1.x; As[0][kq1 + 1][r1] = ra1.y;
        As[0][kq1 + 2][r1] = ra1.z; As[0][kq1 + 3][r1] = ra1.w;
        Bs[0][kq0 + 0][r0] = rb0.x; Bs[0][kq0 + 1][r0] = rb0.y;
        Bs[0][kq0 + 2][r0] = rb0.z; Bs[0][kq0 + 3][r0] = rb0.w;
        Bs[0][kq1 + 0][r1] = rb1.x; Bs[0][kq1 + 1][r1] = rb1.y;
        Bs[0][kq1 + 2][r1] = rb1.z; Bs[0][kq1 + 3][r1] = rb1.w;
    }
    __syncthreads();

    int buf = 0;
    for (int kt = 0; kt < KT; kt++) {
        if (kt + 1 < KT) {
            int k0 = (kt + 1) * 16;
            ra0 = (k0 + kq0 < IND) ? *(const float4*)(A0 + k0 + kq0) : z4;
            ra1 = (k0 + kq1 < IND) ? *(const float4*)(A1 + k0 + kq1) : z4;
            rb0 = (k0 + kq0 < IND) ? *(const float4*)(B0 + k0 + kq0) : z4;
            rb1 = (k0 + kq1 < IND) ? *(const float4*)(B1 + k0 + kq1) : z4;
        }
        #pragma unroll
        for (int k = 0; k < 16; k++) {
            float4 a0 = *(const float4*)&As[buf][k][bq * 8];
            float4 a1 = *(const float4*)&As[buf][k][bq * 8 + 4];
            float4 bv0 = *(const float4*)&Bs[buf][k][nq * 8];
            float4 bv1 = *(const float4*)&Bs[buf][k][nq * 8 + 4];
            float am[8] = {a0.x, a0.y, a0.z, a0.w, a1.x, a1.y, a1.z, a1.w};
            float bn[8] = {bv0.x, bv0.y, bv0.z, bv0.w, bv1.x, bv1.y, bv1.z, bv1.w};
            #pragma unroll
            for (int i = 0; i < 8; i++)
                #pragma unroll
                for (int j = 0; j < 8; j++)
                    acc[i][j] += am[i] * bn[j];
        }
        if (kt + 1 < KT) {
            int nb = buf ^ 1;
            As[nb][kq0 + 0][r0] = ra0.x; As[nb][kq0 + 1][r0] = ra0.y;
            As[nb][kq0 + 2][r0] = ra0.z; As[nb][kq0 + 3][r0] = ra0.w;
            As[nb][kq1 + 0][r1] = ra1.x; As[nb][kq1 + 1][r1] = ra1.y;
            As[nb][kq1 + 2][r1] = ra1.z; As[nb][kq1 + 3][r1] = ra1.w;
            Bs[nb][kq0 + 0][r0] = rb0.x; Bs[nb][kq0 + 1][r0] = rb0.y;
            Bs[nb][kq0 + 2][r0] = rb0.z; Bs[nb][kq0 + 3][r0] = rb0.w;
            Bs[nb][kq1 + 0][r1] = rb1.x; Bs[nb][kq1 + 1][r1] = rb1.y;
            Bs[nb][kq1 + 2][r1] = rb1.z; Bs[nb][kq1 + 3][r1] = rb1.w;
            __syncthreads();
            buf = nb;
        }
    }

    float* out = &d_xs[dir][0][0][0];
    #pragma unroll
    for (int j = 0; j < 8; j++) {
        int n = n0 + nq * 8 + j;
        float bz = bias[n];
        #pragma unroll
        for (int i4 = 0; i4 < 8; i4 += 4) {
            int ml = bq * 8 + i4;
            int m = m0 + ml;
            int t = m >> 6, bb = m & 63;
            float4 o;
            o.x = acc[i4 + 0][j] + bz; o.y = acc[i4 + 1][j] + bz;
            o.z = acc[i4 + 2][j] + bz; o.w = acc[i4 + 3][j] + bz;
            *(float4*)&out[((size_t)t * 1024 + n) * 64 + bb] = o;
        }
    }
}

// ---------------- 4. persistent bidirectional LSTM v5 (FFMA2 + reg preload) ----------------
// 128 blocks (64/dir), 128 threads: uj = tid>>5 (4 units), bp = tid&31.
// Inner loop preloads 16 h pairs into registers per section so the single
// warp/SMSP has >=29cyc of prefetch distance; fma order unchanged (bit-exact).
__global__ void __launch_bounds__(128, 1) k_lstm(const float* __restrict__ whh_f,
                                                 const float* __restrict__ whh_b,
                                                 const int* __restrict__ lens) {
    extern __shared__ float sm[];
    float* Ws2 = sm;          // dup pairs: ull index (g*4+uj)*256 + k   32KB
    float* hsm = sm + 8192;   // [k][b] floats                          64KB
    int blk = blockIdx.x;
    int dir = blk >> 6;
    int f   = blk & 63;
    int ub  = f * 4;
    int tid = threadIdx.x;
    int uj  = tid >> 5;              // unit 0..3
    int bp  = tid & 31;              // sample pair 0..31
    const float* whh = dir ? whh_b : whh_f;

    for (int i = tid; i < 4 * 4 * HH; i += 128) {
        int k = i & (HH - 1);
        int j = (i >> 8) & 3;
        int g = i >> 10;
        float w = whh[(size_t)(g * HH + ub + j) * HH + k];
        Ws2[2 * i]     = w;
        Ws2[2 * i + 1] = w;
    }
    int len0 = lens[2 * bp];
    int len1 = lens[2 * bp + 1];
    int u = ub + uj;
    float c0 = 0.f, h0v = 0.f, c1 = 0.f, h1v = 0.f;
    unsigned gen0 = *(volatile unsigned*)&d_flag[dir][f];
    const float* xs_base = &d_xs[dir][0][0][0];
    float* hq_base = &d_hseq[dir][0][0][0];
    uint32_t hsm_s = (uint32_t)__cvta_generic_to_shared(hsm);
    volatile unsigned* flags = (volatile unsigned*)&d_flag[dir][0];
    const ull* W2 = (const ull*)Ws2;
    __syncthreads();

    for (int s = 0; s < TT; s++) {
        int t = dir ? (TT - 1 - s) : s;
        const float* xsp = xs_base + (size_t)t * 1024 * 64;
        // prefetch gate inputs (flag-independent)
        float2 x0 = *(const float2*)(xsp + (0 * HH + u) * 64 + 2 * bp);
        float2 x1 = *(const float2*)(xsp + (1 * HH + u) * 64 + 2 * bp);
        float2 x2 = *(const float2*)(xsp + (2 * HH + u) * 64 + 2 * bp);
        float2 x3 = *(const float2*)(xsp + (3 * HH + u) * 64 + 2 * bp);
        ull a0 = 0ull, a1 = 0ull, a2 = 0ull, a3 = 0ull;
        if (s > 0) {
            // ---- per-thread spin: thread j waits on producer block j only ----
            unsigned target = gen0 + (unsigned)s;
            if (tid < NBLK_DIR) {
                while (flags[tid] < target) { }
            }
            __syncthreads();
            __threadfence();   // acquire side; no pending stores -> cheap
            // ---- stage h via cp.async, 4 chunks of 16KB ----
            int tp = dir ? (t + 1) : (t - 1);
            const float4* hp4 = (const float4*)(hq_base + (size_t)tp * HH * BB);
            #pragma unroll
            for (int cc = 0; cc < 4; cc++) {
                #pragma unroll
                for (int i = 0; i < 8; i++) {
                    int idx = cc * 1024 + i * 128 + tid;
                    cp16(hsm_s + idx * 16, hp4 + idx);
                }
                cp_commit();
            }
            const ull* H2 = (const ull*)hsm;
            // ---- chunk-overlapped compute; fma order identical (bit-exact) ----
            #pragma unroll
            for (int c4 = 0; c4 < 4; c4++) {
                if (c4 == 0) cp_wait<3>();
                else if (c4 == 1) cp_wait<2>();
                else if (c4 == 2) cp_wait<1>();
                else cp_wait<0>();
                __syncthreads();
                const ull* w0 = W2 + (0 * 4 + uj) * 256 + c4 * 64;
                const ull* w1 = W2 + (1 * 4 + uj) * 256 + c4 * 64;
                const ull* w2 = W2 + (2 * 4 + uj) * 256 + c4 * 64;
                const ull* w3 = W2 + (3 * 4 + uj) * 256 + c4 * 64;
                const ull* hc = H2 + c4 * 64 * 32;
                #pragma unroll
                for (int kk = 0; kk < 64; kk += 16) {
                    // burst: 16 independent h loads into registers
                    ull hr[16];
                    #pragma unroll
                    for (int i = 0; i < 16; i++)
                        hr[i] = hc[(kk + i) * 32 + bp];
                    // long FFMA2 run fed by ready registers + w broadcasts
                    #pragma unroll
                    for (int i = 0; i < 16; i += 2) {
                        ulonglong2 q0 = *(const ulonglong2*)(w0 + kk + i);
                        ulonglong2 q1 = *(const ulonglong2*)(w1 + kk + i);
                        ulonglong2 q2 = *(const ulonglong2*)(w2 + kk + i);
                        ulonglong2 q3 = *(const ulonglong2*)(w3 + kk + i);
                        a0 = fma2(hr[i], q0.x, a0); a0 = fma2(hr[i + 1], q0.y, a0);
                        a1 = fma2(hr[i], q1.x, a1); a1 = fma2(hr[i + 1], q1.y, a1);
                        a2 = fma2(hr[i], q2.x, a2); a2 = fma2(hr[i + 1], q2.y, a2);
                        a3 = fma2(hr[i], q3.x, a3); a3 = fma2(hr[i + 1], q3.y, a3);
                    }
                }
            }
        }
        float2 av0, av1, av2, av3;
        memcpy(&av0, &a0, 8); memcpy(&av1, &a1, 8);
        memcpy(&av2, &a2, 8); memcpy(&av3, &a3, 8);
        // sample 0
        {
            float g0 = x0.x + av0.x, g1 = x1.x + av1.x;
            float g2 = x2.x + av2.x, g3 = x3.x + av3.x;
            float ig = 1.f / (1.f + expf(-g0));
            float fg = 1.f / (1.f + expf(-g1));
            float gg = tanhf(g2);
            float og = 1.f / (1.f + expf(-g3));
            float cn = fg * c0 + ig * gg;
            float hn = og * tanhf(cn);
            if (t < len0) { c0 = cn; h0v = hn; }
        }
        // sample 1
        {
            float g0 = x0.y + av0.y, g1 = x1.y + av1.y;
            float g2 = x2.y + av2.y, g3 = x3.y + av3.y;
            float ig = 1.f / (1.f + expf(-g0));
            float fg = 1.f / (1.f + expf(-g1));
            float gg = tanhf(g2);
            float og = 1.f / (1.f + expf(-g3));
            float cn = fg * c1 + ig * gg;
            float hn = og * tanhf(cn);
            if (t < len1) { c1 = cn; h1v = hn; }
        }
        float2 hw; hw.x = h0v; hw.y = h1v;
        *(float2*)(hq_base + ((size_t)t * HH + u) * BB + 2 * bp) = hw;

        // publish: one fence + flag bump by thread 0
        __syncthreads();
        if (tid == 0) {
            __threadfence();
            atomicExch((unsigned*)&d_flag[dir][f], gen0 + (unsigned)s + 1u);
        }
    }
}

// ---------------- 5. projection + mask -> feats[t][b][n] ----------------
__global__ void __launch_bounds__(256) k_proj(const float* __restrict__ proj_w,
                                              const float* __restrict__ proj_b,
                                              const int* __restrict__ lens) {
    __shared__ float hsm[64][64];
    __shared__ float pw[NT][64];
    int t = blockIdx.x;
    int tid = threadIdx.x;
    int b = tid & 63, grp = tid >> 6;
    float acc[13];
    #pragma unroll
    for (int r = 0; r < 13; r++) acc[r] = 0.f;

    for (int kc = 0; kc < 8; kc++) {
        int u512 = kc * 64;
        int dir = u512 >> 8;
        int ubo = u512 & 255;
        const float* hp = &d_hseq[dir][t][ubo][0];
        #pragma unroll
        for (int i = 0; i < 16; i++) {
            int idx = tid + i * 256;
            hsm[idx >> 6][idx & 63] = hp[idx];
        }
        for (int i = tid; i < NT * 64; i += 256) {
            int n = i >> 6, k = i & 63;
            pw[n][k] = proj_w[(size_t)n * (2 * HH) + kc * 64 + k];
        }
        __syncthreads();
        for (int k = 0; k < 64; k++) {
            float hv = hsm[k][b];
            #pragma unroll
            for (int r = 0; r < 13; r++)
                acc[r] += hv * pw[grp * 13 + r][k];
        }
        __syncthreads();
    }
    int msk = (t < lens[b]) ? 1 : 0;
    #pragma unroll
    for (int r = 0; r < 13; r++) {
        int n = grp * 13 + r;
        d_feats[((size_t)t * 64 + b) * NT + n] = (msk ? acc[r] : 0.f) + proj_b[n];
    }
}

// ---------------- 6. CRF: forward Z + viterbi + gold + tags ----------------
__global__ void __launch_bounds__(64) k_crf(const float* __restrict__ transitions,
                                            const int* __restrict__ lens,
                                            const int* __restrict__ labels,
                                            float* __restrict__ out) {
    __shared__ float tr[NT * NT];
    __shared__ float E[NT * NT];
    __shared__ float alpha[2][64], vv[2][64], ea[64], red[64];
    __shared__ unsigned char bps[TT][NT];
    __shared__ int s_best_last;
    int b = blockIdx.x;
    int j = threadIdx.x;

    for (int i = j; i < NT * NT; i += 64) {
        float x = transitions[i];
        tr[i] = x;
        E[i] = expf(x);
    }
    __syncthreads();
    int len = lens[b];

    float aj = -INFINITY;
    if (j < NT) aj = d_feats[(size_t)(0 * 64 + b) * NT + j] + tr[TSTART * NT + j];
    alpha[0][j] = aj;
    vv[0][j] = aj;
    __syncthreads();

    int p = 0;
    for (int t = 1; t < len; t++) {
        int q = p ^ 1;
        float m = alpha[p][0];
        ea[j] = (j < NT) ? expf(alpha[p][j] - m) : 0.f;
        __syncthreads();
        if (j < NT) {
            float ff = d_feats[((size_t)t * 64 + b) * NT + j];
            float s = 0.f;
            #pragma unroll 4
            for (int i = 0; i < NT; i++) s += ea[i] * E[i * NT + j];
            float best = -INFINITY; int bp = 0;
            for (int i = 0; i < NT; i++) {
                float sij = ff + tr[i * NT + j];
                float cnd = vv[p][i] + sij;
                if (cnd > best) { best = cnd; bp = i; }
            }
            alpha[q][j] = m + logf(s) + ff;
            vv[q][j] = best;
            bps[t][j] = (unsigned char)bp;
        }
        __syncthreads();
        p = q;
    }

    float zx = (j < NT) ? alpha[p][j] + tr[j * NT + TSTOP] : -INFINITY;
    red[j] = zx;
    __syncthreads();
    for (int off = 32; off >= 1; off >>= 1) {
        if (j < off) red[j] = fmaxf(red[j], red[j + off]);
        __syncthreads();
    }
    float zm = red[0];
    __syncthreads();
    red[j] = (j < NT) ? expf(zx - zm) : 0.f;
    __syncthreads();
    for (int off = 32; off >= 1; off >>= 1) {
        if (j < off) red[j] += red[j + off];
        __syncthreads();
    }
    float Z = zm + logf(red[0]);
    __syncthreads();

    red[j] = (j < NT) ? vv[p][j] + tr[j * NT + TSTOP] : -INFINITY;
    __syncthreads();
    if (j == 0) {
        float bv = -INFINITY; int bi = 0;
        for (int i = 0; i < NT; i++)
            if (red[i] > bv) { bv = red[i]; bi = i; }
        s_best_last = bi;
    }
    __syncthreads();
    int best_last = s_best_last;
    __syncthreads();

    float gp = 0.f;
    for (int t = j; t < TT; t += 64) {
        if (t < len) {
            int lab = labels[b * TT + t];
            gp += d_feats[((size_t)t * 64 + b) * NT + lab];
            if (t >= 1) gp += tr[labels[b * TT + t - 1] * NT + lab];
        }
    }
    red[j] = gp;
    __syncthreads();
    for (int off = 32; off >= 1; off >>= 1) {
        if (j < off) red[j] += red[j + off];
        __syncthreads();
    }
    if (j == 0) {
        int l0 = labels[b * TT + 0];
        int ll = labels[b * TT + len - 1];
        float gold = red[0] + tr[TSTART * NT + l0] + tr[ll * NT + TSTOP];
        d_lossp[b] = Z - gold;
    }

    if (j == 0) {
        int cur = best_last;
        for (int t = TT - 1; t >= 0; --t) {
            out[1 + b * TT + t] = (t < len) ? (float)cur : 0.f;
            if (t > 0 && t < len) cur = (int)bps[t][cur];
        }
    }
}

// ---------------- 7. loss reduction ----------------
__global__ void k_loss(float* __restrict__ out) {
    __shared__ float red[64];
    int j = threadIdx.x;
    red[j] = d_lossp[j];
    __syncthreads();
    for (int off = 32; off >= 1; off >>= 1) {
        if (j < off) red[j] += red[j + off];
        __syncthreads();
    }
    if (j == 0) out[0] = red[0];
}

// ---------------- launch ----------------
extern "C" void kernel_launch(void* const* d_in, const int* in_sizes, int n_in,
                              void* d_out, int out_size) {
    const int*   batch_word     = (const int*)  d_in[0];
    const int*   batch_features = (const int*)  d_in[1];
    const int*   batch_wordlen  = (const int*)  d_in[2];
    const int*   batch_char     = (const int*)  d_in[3];
    const int*   charrecover    = (const int*)  d_in[5];
    const int*   batch_label    = (const int*)  d_in[7];
    const float* char_emb       = (const float*)d_in[8];
    const float* conv_w         = (const float*)d_in[9];
    const float* conv_b         = (const float*)d_in[10];
    const float* word_emb       = (const float*)d_in[11];
    const float* feat_emb       = (const float*)d_in[12];
    const float* w_ih_f         = (const float*)d_in[13];
    const float* w_hh_f         = (const float*)d_in[14];
    const float* b_f            = (const float*)d_in[15];
    const float* w_ih_b         = (const float*)d_in[16];
    const float* w_hh_b         = (const float*)d_in[17];
    const float* b_b            = (const float*)d_in[18];
    const float* proj_w         = (const float*)d_in[19];
    const float* proj_b         = (const float*)d_in[20];
    const float* transitions    = (const float*)d_in[21];
    float* out = (float*)d_out;
    (void)in_sizes; (void)n_in; (void)out_size;

    static int smem_set = 0;
    if (!smem_set) {
        cudaFuncSetAttribute(k_lstm, cudaFuncAttributeMaxDynamicSharedMemorySize,
                             (8192 + 16384) * (int)sizeof(float));
        smem_set = 1;
    }

    k_table<<<(3 * VC * CHN + 255) / 256, 256>>>(conv_w, char_emb);
    k_build_x<<<TT * BB, 128>>>(batch_word, batch_features, batch_char,
                                charrecover, word_emb, feat_emb, conv_b);
    {
        dim3 g(128, 8, 2);
        k_gemm2<<<g, 256>>>(w_ih_f, b_f, w_ih_b, b_b);
    }
    k_lstm<<<2 * NBLK_DIR, 128, (8192 + 16384) * sizeof(float)>>>(w_hh_f, w_hh_b,
                                                                  batch_wordlen);
    k_proj<<<TT, 256>>>(proj_w, proj_b, batch_wordlen);
    k_crf<<<BB, 64>>>(transitions, batch_wordlen, batch_label, out);
    k_loss<<<1, 64>>>(out);
}

// round 10
// speedup vs baseline: 1.4383x; 1.0156x over previous
#include <cuda_runtime.h>
#include <math.h>
#include <stdint.h>
#include <string.h>

// ---------------- problem constants ----------------
#define BB 64
#define TT 256
#define LL 16
#define VC 100
#define DC 50
#define CHN 100
#define DW 300
#define DF 20
#define HH 256
#define IND 420          // DW + CHN + DF
#define NT 52            // LAB + 2
#define TSTART 50
#define TSTOP 51

// LSTM v6 partitioning: 4 batch groups x 16 blocks, 16 units/block
#define GRP 4
#define BPG 16           // blocks per (dir,group) barrier domain
#define UPB 16           // units per block
#define SPG 16           // samples per group
#define WSTRIDE 258      // ull stride per (gate,unit) weight row (bank padding)

typedef unsigned long long ull;

// ---------------- scratch (device globals; no allocations) ----------------
__device__ float d_tbl[3][VC][CHN];                 // conv lookup table
__device__ float d_x[(size_t)TT * BB * IND];        // x, row = t*BB + b
__device__ float d_xs[2][TT][4 * HH][BB];           // input proj, transposed [t][n][b]
__device__ float d_hseq[2][TT][HH][BB];             // per-step hidden states
__device__ float d_feats[(size_t)TT * BB * NT];     // emissions [t][b][n]
__device__ float d_lossp[BB];
__device__ unsigned d_flag[2][GRP * BPG];           // per-block monotonic step flags

// ---------------- helpers ----------------
__device__ __forceinline__ void cp16(uint32_t dst_smem, const void* src) {
    asm volatile("cp.async.cg.shared.global [%0], [%1], 16;\n"
                 :: "r"(dst_smem), "l"(src));
}
__device__ __forceinline__ void cp_commit() {
    asm volatile("cp.async.commit_group;\n");
}
template <int N>
__device__ __forceinline__ void cp_wait() {
    asm volatile("cp.async.wait_group %0;\n" :: "n"(N));
}
// packed dual fp32 fma: per-lane IEEE fp32, same rounding as scalar fmaf
__device__ __forceinline__ ull fma2(ull h, ull w, ull acc) {
    ull d;
    asm("fma.rn.f32x2 %0, %1, %2, %3;" : "=l"(d) : "l"(h), "l"(w), "l"(acc));
    return d;
}

// ---------------- 1. conv -> lookup table ----------------
__global__ void k_table(const float* __restrict__ conv_w,
                        const float* __restrict__ char_emb) {
    int idx = blockIdx.x * blockDim.x + threadIdx.x;
    if (idx >= 3 * VC * CHN) return;
    int ch = idx % CHN;
    int c  = (idx / CHN) % VC;
    int kk = idx / (CHN * VC);
    float s = 0.f;
    #pragma unroll 10
    for (int dc = 0; dc < DC; dc++)
        s += conv_w[(ch * DC + dc) * 3 + kk] * char_emb[c * DC + dc];
    d_tbl[kk][c][ch] = s;
}

// ---------------- 2. build x = [word_emb | char_cnn | feat_emb] ----------------
__global__ void k_build_x(const int* __restrict__ word,
                          const int* __restrict__ featidx,
                          const int* __restrict__ chars,
                          const int* __restrict__ recover,
                          const float* __restrict__ word_emb,
                          const float* __restrict__ feat_emb,
                          const float* __restrict__ conv_b) {
    int m = blockIdx.x;           // row = t*BB + b
    int t = m / BB, b = m % BB;
    int tid = threadIdx.x;
    __shared__ int cs[LL];
    float* xr = &d_x[(size_t)m * IND];
    int w = word[b * TT + t];
    const float4* we4 = (const float4*)(word_emb + (size_t)w * DW);
    float4* xr4 = (float4*)xr;
    for (int i = tid; i < DW / 4; i += blockDim.x) xr4[i] = we4[i];
    if (tid < DF) {
        int fv = featidx[b];
        xr[DW + CHN + tid] = feat_emb[fv * DF + tid];
    }
    if (tid < LL) {
        int j = recover[b * TT + t];
        cs[tid] = chars[j * LL + tid];
    }
    __syncthreads();
    if (tid < CHN) {
        float bias = conv_b[tid];
        float mx = -3.4e38f;
        #pragma unroll
        for (int l = 0; l < LL; l++) {
            float v = bias + d_tbl[1][cs[l]][tid];
            if (l > 0)       v += d_tbl[0][cs[l - 1]][tid];
            if (l < LL - 1)  v += d_tbl[2][cs[l + 1]][tid];
            mx = fmaxf(mx, v);
        }
        xr[DW + tid] = mx;
    }
}

// ---------------- 3. input projection GEMM (fused over t, both dirs) ----------------
__global__ void __launch_bounds__(256, 2) k_gemm2(const float* __restrict__ w_f,
                                                  const float* __restrict__ b_fp,
                                                  const float* __restrict__ w_b,
                                                  const float* __restrict__ b_bp) {
    __shared__ float As[2][16][128];
    __shared__ float Bs[2][16][128];
    int dir = blockIdx.z;
    const float* W    = dir ? w_b  : w_f;
    const float* bias = dir ? b_bp : b_fp;
    int m0 = blockIdx.x * 128;
    int n0 = blockIdx.y * 128;
    int tid = threadIdx.x;
    int bq = tid & 15;
    int nq = tid >> 4;

    int r0 = tid >> 2,         kq0 = (tid & 3) << 2;
    int r1 = (tid + 256) >> 2, kq1 = ((tid + 256) & 3) << 2;

    const float* A0 = &d_x[(size_t)(m0 + r0) * IND];
    const float* A1 = &d_x[(size_t)(m0 + r1) * IND];
    const float* B0 = &W[(size_t)(n0 + r0) * IND];
    const float* B1 = &W[(size_t)(n0 + r1) * IND];

    float acc[8][8];
    #pragma unroll
    for (int i = 0; i < 8; i++)
        #pragma unroll
        for (int j = 0; j < 8; j++) acc[i][j] = 0.f;

    const int KT = 27;
    float4 ra0, ra1, rb0, rb1;
    float4 z4 = make_float4(0.f, 0.f, 0.f, 0.f);

    {
        int k0 = 0;
        ra0 = (k0 + kq0 < IND) ? *(const float4*)(A0 + k0 + kq0) : z4;
        ra1 = (k0 + kq1 < IND) ? *(const float4*)(A1 + k0 + kq1) : z4;
        rb0 = (k0 + kq0 < IND) ? *(const float4*)(B0 + k0 + kq0) : z4;
        rb1 = (k0 + kq1 < IND) ? *(const float4*)(B1 + k0 + kq1) : z4;
        As[0][kq0 + 0][r0] = ra0.x; As[0][kq0 + 1][r0] = ra0.y;
        As[0][kq0 + 2][r0] = ra0.z; As[0][kq0 + 3][r0] = ra0.w;
        As[0][kq1 + 0][r1] = ra1.x; As[0][kq1 + 1][r1] = ra1.y;
        As[0][kq1 + 2][r1] = ra1.z; As[0][kq1 + 3][r1] = ra1.w;
        Bs[0][kq0 + 0][r0] = rb0.x; Bs[0][kq0 + 1][r0] = rb0.y;
        Bs[0][kq0 + 2][r0] = rb0.z; Bs[0][kq0 + 3][r0] = rb0.w;
        Bs[0][kq1 + 0][r1] = rb1.x; Bs[0][kq1 + 1][r1] = rb1.y;
        Bs[0][kq1 + 2][r1] = rb1.z; Bs[0][kq1 + 3][r1] = rb1.w;
    }
    __syncthreads();

    int buf = 0;
    for (int kt = 0; kt < KT; kt++) {
        if (kt + 1 < KT) {
            int k0 = (kt + 1) * 16;
            ra0 = (k0 + kq0 < IND) ? *(const float4*)(A0 + k0 + kq0) : z4;
            ra1 = (k0 + kq1 < IND) ? *(const float4*)(A1 + k0 + kq1) : z4;
            rb0 = (k0 + kq0 < IND) ? *(const float4*)(B0 + k0 + kq0) : z4;
            rb1 = (k0 + kq1 < IND) ? *(const float4*)(B1 + k0 + kq1) : z4;
        }
        #pragma unroll
        for (int k = 0; k < 16; k++) {
            float4 a0 = *(const float4*)&As[buf][k][bq * 8];
            float4 a1 = *(const float4*)&As[buf][k][bq * 8 + 4];
            float4 bv0 = *(const float4*)&Bs[buf][k][nq * 8];
            float4 bv1 = *(const float4*)&Bs[buf][k][nq * 8 + 4];
            float am[8] = {a0.x, a0.y, a0.z, a0.w, a1.x, a1.y, a1.z, a1.w};
            float bn[8] = {bv0.x, bv0.y, bv0.z, bv0.w, bv1.x, bv1.y, bv1.z, bv1.w};
            #pragma unroll
            for (int i = 0; i < 8; i++)
                #pragma unroll
                for (int j = 0; j < 8; j++)
                    acc[i][j] += am[i] * bn[j];
        }
        if (kt + 1 < KT) {
            int nb = buf ^ 1;
            As[nb][kq0 + 0][r0] = ra0.x; As[nb][kq0 + 1][r0] = ra0.y;
            As[nb][kq0 + 2][r0] = ra0.z; As[nb][kq0 + 3][r0] = ra0.w;
            As[nb][kq1 + 0][r1] = ra1.x; As[nb][kq1 + 1][r1] = ra1.y;
            As[nb][kq1 + 2][r1] = ra1.z; As[nb][kq1 + 3][r1] = ra1.w;
            Bs[nb][kq0 + 0][r0] = rb0.x; Bs[nb][kq0 + 1][r0] = rb0.y;
            Bs[nb][kq0 + 2][r0] = rb0.z; Bs[nb][kq0 + 3][r0] = rb0.w;
            Bs[nb][kq1 + 0][r1] = rb1.x; Bs[nb][kq1 + 1][r1] = rb1.y;
            Bs[nb][kq1 + 2][r1] = rb1.z; Bs[nb][kq1 + 3][r1] = rb1.w;
            __syncthreads();
            buf = nb;
        }
    }

    float* out = &d_xs[dir][0][0][0];
    #pragma unroll
    for (int j = 0; j < 8; j++) {
        int n = n0 + nq * 8 + j;
        float bz = bias[n];
        #pragma unroll
        for (int i4 = 0; i4 < 8; i4 += 4) {
            int ml = bq * 8 + i4;
            int m = m0 + ml;
            int t = m >> 6, bb = m & 63;
            float4 o;
            o.x = acc[i4 + 0][j] + bz; o.y = acc[i4 + 1][j] + bz;
            o.z = acc[i4 + 2][j] + bz; o.w = acc[i4 + 3][j] + bz;
            *(float4*)&out[((size_t)t * 1024 + n) * 64 + bb] = o;
        }
    }
}

// ---------------- 4. persistent bidirectional LSTM v6 (batch-partitioned domains) --
// 128 blocks = 2 dirs x 4 groups x 16 blocks. Block owns 16 units x 16 samples.
// Barrier domain = 16 blocks; h exchange = 16KB/step/block. Threads: 128 =
// 16 units x 8 sample-pairs (fma2). Per-(unit,sample) fma chain identical to
// prior rounds (k ascending, 64-k chunks) => bit-exact.
__global__ void __launch_bounds__(128, 1) k_lstm(const float* __restrict__ whh_f,
                                                 const float* __restrict__ whh_b,
                                                 const int* __restrict__ lens) {
    extern __shared__ float sm[];
    float* Ws2f = sm;                       // 64 rows x WSTRIDE ull (dup pairs) 132KB
    float* hsm  = sm + 2 * 64 * WSTRIDE;    // 16 samples x 256 units, 16KB
    int blk = blockIdx.x;
    int dir = blk >> 6;
    int g   = (blk >> 4) & 3;
    int lb  = blk & 15;
    int ub  = lb * UPB;
    int tid = threadIdx.x;
    int uj  = tid >> 3;              // unit 0..15
    int bp  = tid & 7;               // sample pair 0..7
    int sb  = g * SPG + 2 * bp;      // global sample index (even)
    const float* whh = dir ? whh_b : whh_f;

    // load W (dup pairs), rows r = gate*16 + ju
    for (int i = tid; i < 4 * UPB * HH; i += 128) {
        int k = i & (HH - 1);
        int r = i >> 8;
        int gate = r >> 4, ju = r & 15;
        float w = whh[(size_t)(gate * HH + ub + ju) * HH + k];
        Ws2f[2 * (r * WSTRIDE + k)]     = w;
        Ws2f[2 * (r * WSTRIDE + k) + 1] = w;
    }
    int len0 = lens[sb];
    int len1 = lens[sb + 1];
    int u = ub + uj;
    float c0 = 0.f, h0v = 0.f, c1 = 0.f, h1v = 0.f;
    volatile unsigned* flags = (volatile unsigned*)&d_flag[dir][g * BPG];
    unsigned gen0 = flags[lb];
    const float* xs_base = &d_xs[dir][0][0][0];
    float* hq_base = &d_hseq[dir][0][0][0];
    uint32_t hsm_s = (uint32_t)__cvta_generic_to_shared(hsm);
    const ull* W2 = (const ull*)Ws2f;
    __syncthreads();

    for (int s = 0; s < TT; s++) {
        int t = dir ? (TT - 1 - s) : s;
        const float* xsp = xs_base + (size_t)t * 1024 * 64;
        // prefetch gate inputs (flag-independent)
        float2 x0 = *(const float2*)(xsp + (0 * HH + u) * 64 + sb);
        float2 x1 = *(const float2*)(xsp + (1 * HH + u) * 64 + sb);
        float2 x2 = *(const float2*)(xsp + (2 * HH + u) * 64 + sb);
        float2 x3 = *(const float2*)(xsp + (3 * HH + u) * 64 + sb);
        ull a0 = 0ull, a1 = 0ull, a2 = 0ull, a3 = 0ull;
        if (s > 0) {
            // per-thread spin on the 16 domain flags
            unsigned target = gen0 + (unsigned)s;
            if (tid < BPG) {
                while (flags[tid] < target) { __nanosleep(32); }
            }
            __syncthreads();
            __threadfence();
            // stage h slab (16 samples x 256 units = 16KB) in 4 chunks of 4KB
            int tp = dir ? (t + 1) : (t - 1);
            const float* hsrc = hq_base + (size_t)tp * HH * BB;
            #pragma unroll
            for (int cc = 0; cc < 4; cc++) {
                #pragma unroll
                for (int i = 0; i < 2; i++) {
                    int idx = i * 128 + tid;          // 0..255 within chunk
                    int r = idx >> 2, c = idx & 3;    // unit-within-chunk, 16B col
                    cp16(hsm_s + (uint32_t)(cc * 4096 + r * 64 + c * 16),
                         hsrc + (size_t)(cc * 64 + r) * 64 + g * SPG + c * 4);
                }
                cp_commit();
            }
            const ull* H2 = (const ull*)hsm;
            // chunk-overlapped compute; fma order identical (bit-exact)
            #pragma unroll
            for (int c4 = 0; c4 < 4; c4++) {
                if (c4 == 0) cp_wait<3>();
                else if (c4 == 1) cp_wait<2>();
                else if (c4 == 2) cp_wait<1>();
                else cp_wait<0>();
                __syncthreads();
                const ull* w0 = W2 + (0 * UPB + uj) * WSTRIDE + c4 * 64;
                const ull* w1 = W2 + (1 * UPB + uj) * WSTRIDE + c4 * 64;
                const ull* w2 = W2 + (2 * UPB + uj) * WSTRIDE + c4 * 64;
                const ull* w3 = W2 + (3 * UPB + uj) * WSTRIDE + c4 * 64;
                const ull* hc = H2 + c4 * 64 * 8;
                #pragma unroll
                for (int kk = 0; kk < 64; kk += 16) {
                    ull hr[16];
                    #pragma unroll
                    for (int i = 0; i < 16; i++)
                        hr[i] = hc[(kk + i) * 8 + bp];
                    #pragma unroll
                    for (int i = 0; i < 16; i += 2) {
                        ulonglong2 q0 = *(const ulonglong2*)(w0 + kk + i);
                        ulonglong2 q1 = *(const ulonglong2*)(w1 + kk + i);
                        ulonglong2 q2 = *(const ulonglong2*)(w2 + kk + i);
                        ulonglong2 q3 = *(const ulonglong2*)(w3 + kk + i);
                        a0 = fma2(hr[i], q0.x, a0); a0 = fma2(hr[i + 1], q0.y, a0);
                        a1 = fma2(hr[i], q1.x, a1); a1 = fma2(hr[i + 1], q1.y, a1);
                        a2 = fma2(hr[i], q2.x, a2); a2 = fma2(hr[i + 1], q2.y, a2);
                        a3 = fma2(hr[i], q3.x, a3); a3 = fma2(hr[i + 1], q3.y, a3);
                    }
                }
            }
        }
        float2 av0, av1, av2, av3;
        memcpy(&av0, &a0, 8); memcpy(&av1, &a1, 8);
        memcpy(&av2, &a2, 8); memcpy(&av3, &a3, 8);
        // sample 0
        {
            float g0 = x0.x + av0.x, g1 = x1.x + av1.x;
            float g2 = x2.x + av2.x, g3 = x3.x + av3.x;
            float ig = 1.f / (1.f + expf(-g0));
            float fg = 1.f / (1.f + expf(-g1));
            float gg = tanhf(g2);
            float og = 1.f / (1.f + expf(-g3));
            float cn = fg * c0 + ig * gg;
            float hn = og * tanhf(cn);
            if (t < len0) { c0 = cn; h0v = hn; }
        }
        // sample 1
        {
            float g0 = x0.y + av0.y, g1 = x1.y + av1.y;
            float g2 = x2.y + av2.y, g3 = x3.y + av3.y;
            float ig = 1.f / (1.f + expf(-g0));
            float fg = 1.f / (1.f + expf(-g1));
            float gg = tanhf(g2);
            float og = 1.f / (1.f + expf(-g3));
            float cn = fg * c1 + ig * gg;
            float hn = og * tanhf(cn);
            if (t < len1) { c1 = cn; h1v = hn; }
        }
        float2 hw; hw.x = h0v; hw.y = h1v;
        *(float2*)(hq_base + ((size_t)t * HH + u) * BB + sb) = hw;

        // publish: one fence + flag bump by thread 0
        __syncthreads();
        if (tid == 0) {
            __threadfence();
            atomicExch((unsigned*)&d_flag[dir][g * BPG + lb],
                       gen0 + (unsigned)s + 1u);
        }
    }
}

// ---------------- 5. projection + mask -> feats[t][b][n] ----------------
__global__ void __launch_bounds__(256) k_proj(const float* __restrict__ proj_w,
                                              const float* __restrict__ proj_b,
                                              const int* __restrict__ lens) {
    __shared__ float hsm[64][64];
    __shared__ float pw[NT][64];
    int t = blockIdx.x;
    int tid = threadIdx.x;
    int b = tid & 63, grp = tid >> 6;
    float acc[13];
    #pragma unroll
    for (int r = 0; r < 13; r++) acc[r] = 0.f;

    for (int kc = 0; kc < 8; kc++) {
        int u512 = kc * 64;
        int dir = u512 >> 8;
        int ubo = u512 & 255;
        const float* hp = &d_hseq[dir][t][ubo][0];
        #pragma unroll
        for (int i = 0; i < 16; i++) {
            int idx = tid + i * 256;
            hsm[idx >> 6][idx & 63] = hp[idx];
        }
        for (int i = tid; i < NT * 64; i += 256) {
            int n = i >> 6, k = i & 63;
            pw[n][k] = proj_w[(size_t)n * (2 * HH) + kc * 64 + k];
        }
        __syncthreads();
        for (int k = 0; k < 64; k++) {
            float hv = hsm[k][b];
            #pragma unroll
            for (int r = 0; r < 13; r++)
                acc[r] += hv * pw[grp * 13 + r][k];
        }
        __syncthreads();
    }
    int msk = (t < lens[b]) ? 1 : 0;
    #pragma unroll
    for (int r = 0; r < 13; r++) {
        int n = grp * 13 + r;
        d_feats[((size_t)t * 64 + b) * NT + n] = (msk ? acc[r] : 0.f) + proj_b[n];
    }
}

// ---------------- 6. CRF: forward Z + viterbi + gold + tags ----------------
__global__ void __launch_bounds__(64) k_crf(const float* __restrict__ transitions,
                                            const int* __restrict__ lens,
                                            const int* __restrict__ labels,
                                            float* __restrict__ out) {
    __shared__ float tr[NT * NT];
    __shared__ float E[NT * NT];
    __shared__ float alpha[2][64], vv[2][64], ea[64], red[64];
    __shared__ unsigned char bps[TT][NT];
    __shared__ int s_best_last;
    int b = blockIdx.x;
    int j = threadIdx.x;

    for (int i = j; i < NT * NT; i += 64) {
        float x = transitions[i];
        tr[i] = x;
        E[i] = expf(x);
    }
    __syncthreads();
    int len = lens[b];

    float aj = -INFINITY;
    if (j < NT) aj = d_feats[(size_t)(0 * 64 + b) * NT + j] + tr[TSTART * NT + j];
    alpha[0][j] = aj;
    vv[0][j] = aj;
    __syncthreads();

    int p = 0;
    for (int t = 1; t < len; t++) {
        int q = p ^ 1;
        float m = alpha[p][0];
        ea[j] = (j < NT) ? expf(alpha[p][j] - m) : 0.f;
        __syncthreads();
        if (j < NT) {
            float ff = d_feats[((size_t)t * 64 + b) * NT + j];
            float s = 0.f;
            #pragma unroll 4
            for (int i = 0; i < NT; i++) s += ea[i] * E[i * NT + j];
            float best = -INFINITY; int bp = 0;
            for (int i = 0; i < NT; i++) {
                float sij = ff + tr[i * NT + j];
                float cnd = vv[p][i] + sij;
                if (cnd > best) { best = cnd; bp = i; }
            }
            alpha[q][j] = m + logf(s) + ff;
            vv[q][j] = best;
            bps[t][j] = (unsigned char)bp;
        }
        __syncthreads();
        p = q;
    }

    float zx = (j < NT) ? alpha[p][j] + tr[j * NT + TSTOP] : -INFINITY;
    red[j] = zx;
    __syncthreads();
    for (int off = 32; off >= 1; off >>= 1) {
        if (j < off) red[j] = fmaxf(red[j], red[j + off]);
        __syncthreads();
    }
    float zm = red[0];
    __syncthreads();
    red[j] = (j < NT) ? expf(zx - zm) : 0.f;
    __syncthreads();
    for (int off = 32; off >= 1; off >>= 1) {
        if (j < off) red[j] += red[j + off];
        __syncthreads();
    }
    float Z = zm + logf(red[0]);
    __syncthreads();

    red[j] = (j < NT) ? vv[p][j] + tr[j * NT + TSTOP] : -INFINITY;
    __syncthreads();
    if (j == 0) {
        float bv = -INFINITY; int bi = 0;
        for (int i = 0; i < NT; i++)
            if (red[i] > bv) { bv = red[i]; bi = i; }
        s_best_last = bi;
    }
    __syncthreads();
    int best_last = s_best_last;
    __syncthreads();

    float gp = 0.f;
    for (int t = j; t < TT; t += 64) {
        if (t < len) {
            int lab = labels[b * TT + t];
            gp += d_feats[((size_t)t * 64 + b) * NT + lab];
            if (t >= 1) gp += tr[labels[b * TT + t - 1] * NT + lab];
        }
    }
    red[j] = gp;
    __syncthreads();
    for (int off = 32; off >= 1; off >>= 1) {
        if (j < off) red[j] += red[j + off];
        __syncthreads();
    }
    if (j == 0) {
        int l0 = labels[b * TT + 0];
        int ll = labels[b * TT + len - 1];
        float gold = red[0] + tr[TSTART * NT + l0] + tr[ll * NT + TSTOP];
        d_lossp[b] = Z - gold;
    }

    if (j == 0) {
        int cur = best_last;
        for (int t = TT - 1; t >= 0; --t) {
            out[1 + b * TT + t] = (t < len) ? (float)cur : 0.f;
            if (t > 0 && t < len) cur = (int)bps[t][cur];
        }
    }
}

// ---------------- 7. loss reduction ----------------
__global__ void k_loss(float* __restrict__ out) {
    __shared__ float red[64];
    int j = threadIdx.x;
    red[j] = d_lossp[j];
    __syncthreads();
    for (int off = 32; off >= 1; off >>= 1) {
        if (j < off) red[j] += red[j + off];
        __syncthreads();
    }
    if (j == 0) out[0] = red[0];
}

// ---------------- launch ----------------
extern "C" void kernel_launch(void* const* d_in, const int* in_sizes, int n_in,
                              void* d_out, int out_size) {
    const int*   batch_word     = (const int*)  d_in[0];
    const int*   batch_features = (const int*)  d_in[1];
    const int*   batch_wordlen  = (const int*)  d_in[2];
    const int*   batch_char     = (const int*)  d_in[3];
    const int*   charrecover    = (const int*)  d_in[5];
    const int*   batch_label    = (const int*)  d_in[7];
    const float* char_emb       = (const float*)d_in[8];
    const float* conv_w         = (const float*)d_in[9];
    const float* conv_b         = (const float*)d_in[10];
    const float* word_emb       = (const float*)d_in[11];
    const float* feat_emb       = (const float*)d_in[12];
    const float* w_ih_f         = (const float*)d_in[13];
    const float* w_hh_f         = (const float*)d_in[14];
    const float* b_f            = (const float*)d_in[15];
    const float* w_ih_b         = (const float*)d_in[16];
    const float* w_hh_b         = (const float*)d_in[17];
    const float* b_b            = (const float*)d_in[18];
    const float* proj_w         = (const float*)d_in[19];
    const float* proj_b         = (const float*)d_in[20];
    const float* transitions    = (const float*)d_in[21];
    float* out = (float*)d_out;
    (void)in_sizes; (void)n_in; (void)out_size;

    const int lstm_smem = (2 * 64 * WSTRIDE + 4096) * (int)sizeof(float);
    static int smem_set = 0;
    if (!smem_set) {
        cudaFuncSetAttribute(k_lstm, cudaFuncAttributeMaxDynamicSharedMemorySize,
                             lstm_smem);
        smem_set = 1;
    }

    k_table<<<(3 * VC * CHN + 255) / 256, 256>>>(conv_w, char_emb);
    k_build_x<<<TT * BB, 128>>>(batch_word, batch_features, batch_char,
                                charrecover, word_emb, feat_emb, conv_b);
    {
        dim3 g(128, 8, 2);
        k_gemm2<<<g, 256>>>(w_ih_f, b_f, w_ih_b, b_b);
    }
    k_lstm<<<128, 128, lstm_smem>>>(w_hh_f, w_hh_b, batch_wordlen);
    k_proj<<<TT, 256>>>(proj_w, proj_b, batch_wordlen);
    k_crf<<<BB, 64>>>(transitions, batch_wordlen, batch_label, out);
    k_loss<<<1, 64>>>(out);
}